// round 3
// baseline (speedup 1.0000x reference)
#include <cuda_runtime.h>
#include <cstdint>

#define EMB   768
#define NHEAD 8
#define HD    96
#define BATCH 2
#define SEQ   4096
#define MROWS (BATCH * SEQ)          // 8192
#define QKVN  (4 * EMB)              // 3072

// ---------------- scratch (static device globals; no allocs allowed) -------
__device__ float g_q[BATCH * NHEAD * SEQ * HD];
__device__ float g_k[BATCH * NHEAD * SEQ * HD];
__device__ float g_v[BATCH * NHEAD * SEQ * HD];
__device__ float g_r[BATCH * NHEAD * SEQ * HD];
__device__ float g_att[MROWS * EMB];

// ---------------- tf32 helpers ---------------------------------------------
__device__ __forceinline__ uint32_t f2tf(float x) {
    uint32_t r;
    asm("cvt.rna.tf32.f32 %0, %1;" : "=r"(r) : "f"(x));
    return r;
}

// D += A(tf32) * B(tf32), m16n8k8, fp32 accumulate
__device__ __forceinline__ void mma8(float* d,
                                     uint32_t a0, uint32_t a1, uint32_t a2, uint32_t a3,
                                     uint32_t b0, uint32_t b1) {
    asm volatile(
        "mma.sync.aligned.m16n8k8.row.col.f32.tf32.tf32.f32 "
        "{%0,%1,%2,%3}, {%4,%5,%6,%7}, {%8,%9}, {%0,%1,%2,%3};"
        : "+f"(d[0]), "+f"(d[1]), "+f"(d[2]), "+f"(d[3])
        : "r"(a0), "r"(a1), "r"(a2), "r"(a3), "r"(b0), "r"(b1));
}

// ===========================================================================
// TF32 tensor-core GEMM, BM=128 BN=128 BK=16, 256 threads (8 warps 2x4),
// warp tile 64x32 (m-tiles 4, n-tiles 4).
// COMP=1: 3-product compensated tf32 (~fp32 accuracy). COMP=0: plain tf32.
// EPI=0: bias + qkvr scatter into g_q/g_k/g_v/g_r. EPI=1: bias + store to out.
// As is stored K-major [16][136] so A-frag LDS is conflict-free; Bs [16][136].
// ===========================================================================
template <int COMP, int EPI>
__global__ __launch_bounds__(256, 1)
void gemm_tf32(const float* __restrict__ A, const float* __restrict__ B,
               const float* __restrict__ bias, float* __restrict__ out, int N)
{
    __shared__ float As[16 * 136];   // As[k][m]
    __shared__ float Bs[16 * 136];   // Bs[k][n]

    const int K  = EMB;
    const int m0 = blockIdx.y * 128;
    const int n0 = blockIdx.x * 128;
    const int tid  = threadIdx.x;
    const int warp = tid >> 5;
    const int lane = tid & 31;
    const int g = lane >> 2, q = lane & 3;
    const int wm0 = (warp >> 2) * 64;     // 0 or 64
    const int wn0 = (warp & 3) * 32;      // 0,32,64,96

    float acc[4][4][4];
#pragma unroll
    for (int i = 0; i < 4; i++)
#pragma unroll
        for (int j = 0; j < 4; j++)
#pragma unroll
            for (int e = 0; e < 4; e++) acc[i][j][e] = 0.f;

    for (int k0 = 0; k0 < K; k0 += 16) {
        // load A tile (transpose into As[k][m]) and B tile
#pragma unroll
        for (int it = 0; it < 2; it++) {
            int u = it * 256 + tid;              // 512 float4s each
            int arow = u >> 2, ac4 = u & 3;
            float4 av = *(const float4*)(A + (size_t)(m0 + arow) * K + k0 + ac4 * 4);
            As[(ac4 * 4 + 0) * 136 + arow] = av.x;
            As[(ac4 * 4 + 1) * 136 + arow] = av.y;
            As[(ac4 * 4 + 2) * 136 + arow] = av.z;
            As[(ac4 * 4 + 3) * 136 + arow] = av.w;
            int brow = u >> 5, bc4 = u & 31;
            *(float4*)(&Bs[brow * 136 + bc4 * 4]) =
                *(const float4*)(B + (size_t)(k0 + brow) * N + n0 + bc4 * 4);
        }
        __syncthreads();

#pragma unroll
        for (int kk = 0; kk < 16; kk += 8) {
            uint32_t ahi[4][4], alo[4][4];
#pragma unroll
            for (int mt = 0; mt < 4; mt++) {
                int mrow = wm0 + mt * 16 + g;
                float a0 = As[(kk + q) * 136 + mrow];
                float a1 = As[(kk + q) * 136 + mrow + 8];
                float a2 = As[(kk + q + 4) * 136 + mrow];
                float a3 = As[(kk + q + 4) * 136 + mrow + 8];
                ahi[mt][0] = f2tf(a0); ahi[mt][1] = f2tf(a1);
                ahi[mt][2] = f2tf(a2); ahi[mt][3] = f2tf(a3);
                if (COMP) {
                    alo[mt][0] = f2tf(a0 - __uint_as_float(ahi[mt][0]));
                    alo[mt][1] = f2tf(a1 - __uint_as_float(ahi[mt][1]));
                    alo[mt][2] = f2tf(a2 - __uint_as_float(ahi[mt][2]));
                    alo[mt][3] = f2tf(a3 - __uint_as_float(ahi[mt][3]));
                }
            }
            uint32_t bhi[4][2], blo[4][2];
#pragma unroll
            for (int nt = 0; nt < 4; nt++) {
                int ncol = wn0 + nt * 8 + g;
                float b0 = Bs[(kk + q) * 136 + ncol];
                float b1 = Bs[(kk + q + 4) * 136 + ncol];
                bhi[nt][0] = f2tf(b0); bhi[nt][1] = f2tf(b1);
                if (COMP) {
                    blo[nt][0] = f2tf(b0 - __uint_as_float(bhi[nt][0]));
                    blo[nt][1] = f2tf(b1 - __uint_as_float(bhi[nt][1]));
                }
            }
#pragma unroll
            for (int mt = 0; mt < 4; mt++)
#pragma unroll
                for (int nt = 0; nt < 4; nt++) {
                    mma8(acc[mt][nt], ahi[mt][0], ahi[mt][1], ahi[mt][2], ahi[mt][3],
                         bhi[nt][0], bhi[nt][1]);
                    if (COMP) {
                        mma8(acc[mt][nt], alo[mt][0], alo[mt][1], alo[mt][2], alo[mt][3],
                             bhi[nt][0], bhi[nt][1]);
                        mma8(acc[mt][nt], ahi[mt][0], ahi[mt][1], ahi[mt][2], ahi[mt][3],
                             blo[nt][0], blo[nt][1]);
                    }
                }
        }
        __syncthreads();
    }

    // epilogue
#pragma unroll
    for (int mt = 0; mt < 4; mt++)
#pragma unroll
        for (int nt = 0; nt < 4; nt++)
#pragma unroll
            for (int e = 0; e < 4; e++) {
                int rowg = m0 + wm0 + mt * 16 + g + ((e >= 2) ? 8 : 0);
                int colg = n0 + wn0 + nt * 8 + 2 * q + (e & 1);
                float val = acc[mt][nt][e] + bias[colg];
                if (EPI == 1) {
                    out[(size_t)rowg * N + colg] = val;
                } else {
                    int b_   = rowg >> 12;
                    int n    = rowg & 4095;
                    int qk   = colg & 3;
                    int rest = colg >> 2;
                    int d    = rest % 96;
                    int h    = rest / 96;
                    size_t dst = ((size_t)(b_ * NHEAD + h) * SEQ + n) * HD + d;
                    float* t = (qk == 0) ? g_q : (qk == 1) ? g_k : (qk == 2) ? g_v : g_r;
                    t[dst] = val;
                }
            }
}

// ===========================================================================
// Flash attention with tf32 mma.  grid (SEQ/128, B*H), 256 threads (8 warps),
// each warp owns 16 q-rows; k-blocks of 64 keys.
// QK^T: 3-product compensated tf32 (logit path).  PV: plain tf32.
// smem strides chosen so every fragment LDS pattern is bank-conflict-free.
// ===========================================================================
#define QS_OFF  0                         // Qs[128][104] fp32
#define KHI_OFF (QS_OFF + 128 * 104)      // Khi[64][104]  (K[n][k], tf32 hi)
#define KLO_OFF (KHI_OFF + 64 * 104)      // Klo[64][104]
#define VS_OFF  (KLO_OFF + 64 * 104)      // Vs[64][104]   (V[k][n], tf32-rounded)
#define PS_OFF  (VS_OFF + 64 * 104)       // Ps[128][72]   (tf32-rounded)
#define ATT_SMEM_FLOATS (PS_OFF + 128 * 72)
#define ATT_SMEM_BYTES  (ATT_SMEM_FLOATS * 4)

__global__ __launch_bounds__(256, 1)
void attn_kernel(const float* __restrict__ gq, const float* __restrict__ gk,
                 const float* __restrict__ gv, const float* __restrict__ gr,
                 float* __restrict__ gatt)
{
    extern __shared__ float sm[];
    float* Qs  = sm + QS_OFF;
    float* Khi = sm + KHI_OFF;
    float* Klo = sm + KLO_OFF;
    float* Vs  = sm + VS_OFF;
    float* Ps  = sm + PS_OFF;

    const int tid  = threadIdx.x;
    const int warp = tid >> 5;
    const int lane = tid & 31;
    const int g = lane >> 2, q = lane & 3;
    const int qr0 = warp * 16;                 // warp's local q-row base

    const int bh = blockIdx.y;
    const int qb = blockIdx.x;
    const size_t base = (size_t)bh * SEQ * HD;
    const float* qptr = gq + base + (size_t)qb * 128 * HD;

    // load Q tile [128][96] fp32
#pragma unroll
    for (int i = 0; i < 12; i++) {
        int u = i * 256 + tid;                 // 3072 float4s
        int row = u / 24, c4 = u % 24;
        *(float4*)(Qs + row * 104 + c4 * 4) =
            *(const float4*)(qptr + row * HD + c4 * 4);
    }

    float o[12][4];
    float m_a = -1e30f, m_b = -1e30f, l_a = 0.f, l_b = 0.f;
#pragma unroll
    for (int nt = 0; nt < 12; nt++)
#pragma unroll
        for (int e = 0; e < 4; e++) o[nt][e] = 0.f;

    for (int kb = 0; kb < SEQ / 64; kb++) {
        __syncthreads();                       // prev K/V fully consumed (and Q ready)
        const float* kptr = gk + base + (size_t)kb * 64 * HD;
        const float* vptr = gv + base + (size_t)kb * 64 * HD;
#pragma unroll
        for (int i = 0; i < 6; i++) {
            int u = i * 256 + tid;             // 1536 float4s
            int row = u / 24, c4 = u % 24;
            float4 kv = *(const float4*)(kptr + row * HD + c4 * 4);
            float4 vv = *(const float4*)(vptr + row * HD + c4 * 4);
            uint32_t h0 = f2tf(kv.x), h1 = f2tf(kv.y), h2 = f2tf(kv.z), h3 = f2tf(kv.w);
            float4 khi4 = make_float4(__uint_as_float(h0), __uint_as_float(h1),
                                      __uint_as_float(h2), __uint_as_float(h3));
            float4 klo4 = make_float4(
                __uint_as_float(f2tf(kv.x - khi4.x)), __uint_as_float(f2tf(kv.y - khi4.y)),
                __uint_as_float(f2tf(kv.z - khi4.z)), __uint_as_float(f2tf(kv.w - khi4.w)));
            *(float4*)(Khi + row * 104 + c4 * 4) = khi4;
            *(float4*)(Klo + row * 104 + c4 * 4) = klo4;
            float4 vhi4 = make_float4(__uint_as_float(f2tf(vv.x)), __uint_as_float(f2tf(vv.y)),
                                      __uint_as_float(f2tf(vv.z)), __uint_as_float(f2tf(vv.w)));
            *(float4*)(Vs + row * 104 + c4 * 4) = vhi4;
        }
        __syncthreads();

        // ---- S = Q K^T (compensated tf32), warp tile 16x64, 8 n-tiles ----
        float s[8][4];
#pragma unroll
        for (int nt = 0; nt < 8; nt++)
#pragma unroll
            for (int e = 0; e < 4; e++) s[nt][e] = 0.f;

#pragma unroll
        for (int ks = 0; ks < 12; ks++) {
            int kc = ks * 8;
            float a0 = Qs[(qr0 + g) * 104 + kc + q];
            float a1 = Qs[(qr0 + g + 8) * 104 + kc + q];
            float a2 = Qs[(qr0 + g) * 104 + kc + q + 4];
            float a3 = Qs[(qr0 + g + 8) * 104 + kc + q + 4];
            uint32_t ah0 = f2tf(a0), ah1 = f2tf(a1), ah2 = f2tf(a2), ah3 = f2tf(a3);
            uint32_t al0 = f2tf(a0 - __uint_as_float(ah0));
            uint32_t al1 = f2tf(a1 - __uint_as_float(ah1));
            uint32_t al2 = f2tf(a2 - __uint_as_float(ah2));
            uint32_t al3 = f2tf(a3 - __uint_as_float(ah3));
#pragma unroll
            for (int nt = 0; nt < 8; nt++) {
                int nrow = nt * 8 + g;
                uint32_t bh0 = __float_as_uint(Khi[nrow * 104 + kc + q]);
                uint32_t bh1 = __float_as_uint(Khi[nrow * 104 + kc + q + 4]);
                uint32_t bl0 = __float_as_uint(Klo[nrow * 104 + kc + q]);
                uint32_t bl1 = __float_as_uint(Klo[nrow * 104 + kc + q + 4]);
                mma8(s[nt], ah0, ah1, ah2, ah3, bh0, bh1);
                mma8(s[nt], al0, al1, al2, al3, bh0, bh1);
                mma8(s[nt], ah0, ah1, ah2, ah3, bl0, bl1);
            }
        }

        // ---- online softmax (fully intra-warp; rows g and g+8) ----
        float mx_a = -1e30f, mx_b = -1e30f;
#pragma unroll
        for (int nt = 0; nt < 8; nt++) {
            mx_a = fmaxf(mx_a, fmaxf(s[nt][0], s[nt][1]));
            mx_b = fmaxf(mx_b, fmaxf(s[nt][2], s[nt][3]));
        }
        mx_a = fmaxf(mx_a, __shfl_xor_sync(0xffffffffu, mx_a, 1));
        mx_a = fmaxf(mx_a, __shfl_xor_sync(0xffffffffu, mx_a, 2));
        mx_b = fmaxf(mx_b, __shfl_xor_sync(0xffffffffu, mx_b, 1));
        mx_b = fmaxf(mx_b, __shfl_xor_sync(0xffffffffu, mx_b, 2));
        float nm_a = fmaxf(m_a, mx_a), nm_b = fmaxf(m_b, mx_b);
        float sc_a = __expf(m_a - nm_a), sc_b = __expf(m_b - nm_b);
        m_a = nm_a; m_b = nm_b;

        float sum_a = 0.f, sum_b = 0.f;
#pragma unroll
        for (int nt = 0; nt < 8; nt++) {
            float p0 = __expf(s[nt][0] - nm_a);
            float p1 = __expf(s[nt][1] - nm_a);
            float p2 = __expf(s[nt][2] - nm_b);
            float p3 = __expf(s[nt][3] - nm_b);
            sum_a += p0 + p1; sum_b += p2 + p3;
            int col = nt * 8 + 2 * q;
            Ps[(qr0 + g) * 72 + col]     = __uint_as_float(f2tf(p0));
            Ps[(qr0 + g) * 72 + col + 1] = __uint_as_float(f2tf(p1));
            Ps[(qr0 + g + 8) * 72 + col]     = __uint_as_float(f2tf(p2));
            Ps[(qr0 + g + 8) * 72 + col + 1] = __uint_as_float(f2tf(p3));
        }
        sum_a += __shfl_xor_sync(0xffffffffu, sum_a, 1);
        sum_a += __shfl_xor_sync(0xffffffffu, sum_a, 2);
        sum_b += __shfl_xor_sync(0xffffffffu, sum_b, 1);
        sum_b += __shfl_xor_sync(0xffffffffu, sum_b, 2);
        l_a = l_a * sc_a + sum_a;
        l_b = l_b * sc_b + sum_b;
#pragma unroll
        for (int nt = 0; nt < 12; nt++) {
            o[nt][0] *= sc_a; o[nt][1] *= sc_a;
            o[nt][2] *= sc_b; o[nt][3] *= sc_b;
        }
        __syncwarp();                          // Ps visible within warp

        // ---- O += P V (plain tf32), 12 n-tiles over d=96 ----
#pragma unroll
        for (int ks = 0; ks < 8; ks++) {
            int kc = ks * 8;
            uint32_t pa0 = __float_as_uint(Ps[(qr0 + g) * 72 + kc + q]);
            uint32_t pa1 = __float_as_uint(Ps[(qr0 + g + 8) * 72 + kc + q]);
            uint32_t pa2 = __float_as_uint(Ps[(qr0 + g) * 72 + kc + q + 4]);
            uint32_t pa3 = __float_as_uint(Ps[(qr0 + g + 8) * 72 + kc + q + 4]);
#pragma unroll
            for (int nt = 0; nt < 12; nt++) {
                uint32_t vb0 = __float_as_uint(Vs[(kc + q) * 104 + nt * 8 + g]);
                uint32_t vb1 = __float_as_uint(Vs[(kc + q + 4) * 104 + nt * 8 + g]);
                mma8(o[nt], pa0, pa1, pa2, pa3, vb0, vb1);
            }
        }
        __syncwarp();                          // done with Ps before next overwrite
    }

    // ---- epilogue: /l, *1/sqrt(768), gate by r, store (b, n, h*96+d) ----
    const float inv_sqrt_emb = 0.03608439182435161f;
    const int b_ = bh >> 3, h = bh & 7;
    const float li_a = inv_sqrt_emb / l_a;
    const float li_b = inv_sqrt_emb / l_b;
    const int n_a = qb * 128 + qr0 + g;
    const int n_b = n_a + 8;
#pragma unroll
    for (int nt = 0; nt < 12; nt++) {
        int d = nt * 8 + 2 * q;
        float ra0 = gr[base + (size_t)n_a * HD + d];
        float ra1 = gr[base + (size_t)n_a * HD + d + 1];
        float rb0 = gr[base + (size_t)n_b * HD + d];
        float rb1 = gr[base + (size_t)n_b * HD + d + 1];
        size_t oa = ((size_t)(b_ * SEQ + n_a)) * EMB + h * HD + d;
        size_t ob = ((size_t)(b_ * SEQ + n_b)) * EMB + h * HD + d;
        gatt[oa]     = o[nt][0] * li_a * ra0;
        gatt[oa + 1] = o[nt][1] * li_a * ra1;
        gatt[ob]     = o[nt][2] * li_b * rb0;
        gatt[ob + 1] = o[nt][3] * li_b * rb1;
    }
}

// ===========================================================================
extern "C" void kernel_launch(void* const* d_in, const int* in_sizes, int n_in,
                              void* d_out, int out_size)
{
    const float* x      = (const float*)d_in[0];
    const float* w_qkvr = (const float*)d_in[1];
    const float* b_qkvr = (const float*)d_in[2];
    const float* w_proj = (const float*)d_in[3];
    const float* b_proj = (const float*)d_in[4];
    float* out = (float*)d_out;

    cudaFuncSetAttribute(attn_kernel,
                         cudaFuncAttributeMaxDynamicSharedMemorySize,
                         ATT_SMEM_BYTES);

    float *gq, *gk, *gv, *gr, *gatt;
    cudaGetSymbolAddress((void**)&gq, g_q);
    cudaGetSymbolAddress((void**)&gk, g_k);
    cudaGetSymbolAddress((void**)&gv, g_v);
    cudaGetSymbolAddress((void**)&gr, g_r);
    cudaGetSymbolAddress((void**)&gatt, g_att);

    gemm_tf32<1, 0><<<dim3(QKVN / 128, MROWS / 128), 256>>>(
        x, w_qkvr, b_qkvr, nullptr, QKVN);
    attn_kernel<<<dim3(SEQ / 128, BATCH * NHEAD), 256, ATT_SMEM_BYTES>>>(
        gq, gk, gv, gr, gatt);
    gemm_tf32<0, 1><<<dim3(EMB / 128, MROWS / 128), 256>>>(
        gatt, w_proj, b_proj, out, EMB);
}

// round 5
// speedup vs baseline: 1.0160x; 1.0160x over previous
#include <cuda_runtime.h>
#include <cstdint>

#define EMB   768
#define NHEAD 8
#define HD    96
#define BATCH 2
#define SEQ   4096
#define MROWS (BATCH * SEQ)          // 8192
#define QKVN  (4 * EMB)              // 3072
#define BHTOT (BATCH * NHEAD)        // 16

// ---------------- scratch (static device globals; no allocs) ---------------
__device__ float g_xhi[MROWS * EMB], g_xlo[MROWS * EMB];
__device__ float g_whi[EMB * QKVN],  g_wlo[EMB * QKVN];
__device__ float g_q[BHTOT * SEQ * HD];
__device__ float g_k[BHTOT * SEQ * HD];
__device__ float g_v[BHTOT * SEQ * HD];
__device__ float g_r[BHTOT * SEQ * HD];
__device__ float g_att[MROWS * EMB];

// ---------------- tf32 helpers ---------------------------------------------
__device__ __forceinline__ uint32_t f2tf(float x) {
    uint32_t r;
    asm("cvt.rna.tf32.f32 %0, %1;" : "=r"(r) : "f"(x));
    return r;
}
__device__ __forceinline__ float tfr(float x) { return __uint_as_float(f2tf(x)); }

__device__ __forceinline__ void mma8(float* d,
                                     uint32_t a0, uint32_t a1, uint32_t a2, uint32_t a3,
                                     uint32_t b0, uint32_t b1) {
    asm volatile(
        "mma.sync.aligned.m16n8k8.row.col.f32.tf32.tf32.f32 "
        "{%0,%1,%2,%3}, {%4,%5,%6,%7}, {%8,%9}, {%0,%1,%2,%3};"
        : "+f"(d[0]), "+f"(d[1]), "+f"(d[2]), "+f"(d[3])
        : "r"(a0), "r"(a1), "r"(a2), "r"(a3), "r"(b0), "r"(b1));
}

// ---------------- pre-split elementwise kernel -----------------------------
__global__ void split_kernel(const float* __restrict__ in,
                             float* __restrict__ hi, float* __restrict__ lo, int n4) {
    int i = blockIdx.x * blockDim.x + threadIdx.x;
    if (i >= n4) return;
    float4 v = ((const float4*)in)[i];
    float4 h, l;
    h.x = tfr(v.x); l.x = tfr(v.x - h.x);
    h.y = tfr(v.y); l.y = tfr(v.y - h.y);
    h.z = tfr(v.z); l.z = tfr(v.z - h.z);
    h.w = tfr(v.w); l.w = tfr(v.w - h.w);
    ((float4*)hi)[i] = h;
    ((float4*)lo)[i] = l;
}

// ===========================================================================
// QKV GEMM: pre-split inputs, 4 smem tiles, ZERO cvt in mainloop.
// Identical tiling / fragment addressing / epilogue to the proven R3 kernel:
// BM=128 BN=128 BK=16, 256 threads (2x4 warps, 64x32 warp tile),
// smem layout [k][m] / [k][n], stride 136.
// ===========================================================================
__global__ __launch_bounds__(256, 1)
void gemm_qkv(const float* __restrict__ Ahi_g, const float* __restrict__ Alo_g,
              const float* __restrict__ Bhi_g, const float* __restrict__ Blo_g,
              const float* __restrict__ bias)
{
    __shared__ float Ah[16 * 136];   // Ah[k][m]
    __shared__ float Al[16 * 136];
    __shared__ float Bh[16 * 136];   // Bh[k][n]
    __shared__ float Bl[16 * 136];

    const int K  = EMB, N = QKVN;
    const int m0 = blockIdx.y * 128;
    const int n0 = blockIdx.x * 128;
    const int tid  = threadIdx.x;
    const int warp = tid >> 5;
    const int lane = tid & 31;
    const int g = lane >> 2, q = lane & 3;
    const int wm0 = (warp >> 2) * 64;
    const int wn0 = (warp & 3) * 32;

    float acc[4][4][4];
#pragma unroll
    for (int i = 0; i < 4; i++)
#pragma unroll
        for (int j = 0; j < 4; j++)
#pragma unroll
            for (int e = 0; e < 4; e++) acc[i][j][e] = 0.f;

    for (int k0 = 0; k0 < K; k0 += 16) {
        // load tiles (A transposed into [k][m]) — R3 loader, duplicated hi/lo
#pragma unroll
        for (int it = 0; it < 2; it++) {
            int u = it * 256 + tid;              // 512 float4s each matrix
            int arow = u >> 2, ac4 = u & 3;
            size_t aoff = (size_t)(m0 + arow) * K + k0 + ac4 * 4;
            float4 av = *(const float4*)(Ahi_g + aoff);
            Ah[(ac4 * 4 + 0) * 136 + arow] = av.x;
            Ah[(ac4 * 4 + 1) * 136 + arow] = av.y;
            Ah[(ac4 * 4 + 2) * 136 + arow] = av.z;
            Ah[(ac4 * 4 + 3) * 136 + arow] = av.w;
            float4 av2 = *(const float4*)(Alo_g + aoff);
            Al[(ac4 * 4 + 0) * 136 + arow] = av2.x;
            Al[(ac4 * 4 + 1) * 136 + arow] = av2.y;
            Al[(ac4 * 4 + 2) * 136 + arow] = av2.z;
            Al[(ac4 * 4 + 3) * 136 + arow] = av2.w;
            int brow = u >> 5, bc4 = u & 31;
            size_t boff = (size_t)(k0 + brow) * N + n0 + bc4 * 4;
            *(float4*)(&Bh[brow * 136 + bc4 * 4]) = *(const float4*)(Bhi_g + boff);
            *(float4*)(&Bl[brow * 136 + bc4 * 4]) = *(const float4*)(Blo_g + boff);
        }
        __syncthreads();

#pragma unroll
        for (int kk = 0; kk < 16; kk += 8) {
            uint32_t ahi[4][4], alo[4][4];
#pragma unroll
            for (int mt = 0; mt < 4; mt++) {
                int mrow = wm0 + mt * 16 + g;
                ahi[mt][0] = __float_as_uint(Ah[(kk + q) * 136 + mrow]);
                ahi[mt][1] = __float_as_uint(Ah[(kk + q) * 136 + mrow + 8]);
                ahi[mt][2] = __float_as_uint(Ah[(kk + q + 4) * 136 + mrow]);
                ahi[mt][3] = __float_as_uint(Ah[(kk + q + 4) * 136 + mrow + 8]);
                alo[mt][0] = __float_as_uint(Al[(kk + q) * 136 + mrow]);
                alo[mt][1] = __float_as_uint(Al[(kk + q) * 136 + mrow + 8]);
                alo[mt][2] = __float_as_uint(Al[(kk + q + 4) * 136 + mrow]);
                alo[mt][3] = __float_as_uint(Al[(kk + q + 4) * 136 + mrow + 8]);
            }
            uint32_t bhi[4][2], blo[4][2];
#pragma unroll
            for (int nt = 0; nt < 4; nt++) {
                int ncol = wn0 + nt * 8 + g;
                bhi[nt][0] = __float_as_uint(Bh[(kk + q) * 136 + ncol]);
                bhi[nt][1] = __float_as_uint(Bh[(kk + q + 4) * 136 + ncol]);
                blo[nt][0] = __float_as_uint(Bl[(kk + q) * 136 + ncol]);
                blo[nt][1] = __float_as_uint(Bl[(kk + q + 4) * 136 + ncol]);
            }
#pragma unroll
            for (int mt = 0; mt < 4; mt++)
#pragma unroll
                for (int nt = 0; nt < 4; nt++) {
                    mma8(acc[mt][nt], ahi[mt][0], ahi[mt][1], ahi[mt][2], ahi[mt][3],
                         bhi[nt][0], bhi[nt][1]);
                    mma8(acc[mt][nt], alo[mt][0], alo[mt][1], alo[mt][2], alo[mt][3],
                         bhi[nt][0], bhi[nt][1]);
                    mma8(acc[mt][nt], ahi[mt][0], ahi[mt][1], ahi[mt][2], ahi[mt][3],
                         blo[nt][0], blo[nt][1]);
                }
        }
        __syncthreads();
    }

    // epilogue — R3 verbatim (raw q/k/v/r scatter)
#pragma unroll
    for (int mt = 0; mt < 4; mt++)
#pragma unroll
        for (int nt = 0; nt < 4; nt++)
#pragma unroll
            for (int e = 0; e < 4; e++) {
                int rowg = m0 + wm0 + mt * 16 + g + ((e >= 2) ? 8 : 0);
                int colg = n0 + wn0 + nt * 8 + 2 * q + (e & 1);
                float val = acc[mt][nt][e] + bias[colg];
                int b_   = rowg >> 12;
                int n    = rowg & 4095;
                int qk   = colg & 3;
                int rest = colg >> 2;
                int d    = rest % 96;
                int h    = rest / 96;
                size_t dst = ((size_t)(b_ * NHEAD + h) * SEQ + n) * HD + d;
                float* t = (qk == 0) ? g_q : (qk == 1) ? g_k : (qk == 2) ? g_v : g_r;
                t[dst] = val;
            }
}

// ===========================================================================
// Out-projection GEMM — verbatim R3 gemm_tf32<0,1> (in-loop cvt, plain tf32).
// ===========================================================================
__global__ __launch_bounds__(256, 1)
void gemm_proj(const float* __restrict__ A, const float* __restrict__ B,
               const float* __restrict__ bias, float* __restrict__ out, int N)
{
    __shared__ float As[16 * 136];
    __shared__ float Bs[16 * 136];

    const int K  = EMB;
    const int m0 = blockIdx.y * 128;
    const int n0 = blockIdx.x * 128;
    const int tid  = threadIdx.x;
    const int warp = tid >> 5;
    const int lane = tid & 31;
    const int g = lane >> 2, q = lane & 3;
    const int wm0 = (warp >> 2) * 64;
    const int wn0 = (warp & 3) * 32;

    float acc[4][4][4];
#pragma unroll
    for (int i = 0; i < 4; i++)
#pragma unroll
        for (int j = 0; j < 4; j++)
#pragma unroll
            for (int e = 0; e < 4; e++) acc[i][j][e] = 0.f;

    for (int k0 = 0; k0 < K; k0 += 16) {
#pragma unroll
        for (int it = 0; it < 2; it++) {
            int u = it * 256 + tid;
            int arow = u >> 2, ac4 = u & 3;
            float4 av = *(const float4*)(A + (size_t)(m0 + arow) * K + k0 + ac4 * 4);
            As[(ac4 * 4 + 0) * 136 + arow] = av.x;
            As[(ac4 * 4 + 1) * 136 + arow] = av.y;
            As[(ac4 * 4 + 2) * 136 + arow] = av.z;
            As[(ac4 * 4 + 3) * 136 + arow] = av.w;
            int brow = u >> 5, bc4 = u & 31;
            *(float4*)(&Bs[brow * 136 + bc4 * 4]) =
                *(const float4*)(B + (size_t)(k0 + brow) * N + n0 + bc4 * 4);
        }
        __syncthreads();

#pragma unroll
        for (int kk = 0; kk < 16; kk += 8) {
            uint32_t ahi[4][4];
#pragma unroll
            for (int mt = 0; mt < 4; mt++) {
                int mrow = wm0 + mt * 16 + g;
                ahi[mt][0] = f2tf(As[(kk + q) * 136 + mrow]);
                ahi[mt][1] = f2tf(As[(kk + q) * 136 + mrow + 8]);
                ahi[mt][2] = f2tf(As[(kk + q + 4) * 136 + mrow]);
                ahi[mt][3] = f2tf(As[(kk + q + 4) * 136 + mrow + 8]);
            }
            uint32_t bhi[4][2];
#pragma unroll
            for (int nt = 0; nt < 4; nt++) {
                int ncol = wn0 + nt * 8 + g;
                bhi[nt][0] = f2tf(Bs[(kk + q) * 136 + ncol]);
                bhi[nt][1] = f2tf(Bs[(kk + q + 4) * 136 + ncol]);
            }
#pragma unroll
            for (int mt = 0; mt < 4; mt++)
#pragma unroll
                for (int nt = 0; nt < 4; nt++)
                    mma8(acc[mt][nt], ahi[mt][0], ahi[mt][1], ahi[mt][2], ahi[mt][3],
                         bhi[nt][0], bhi[nt][1]);
        }
        __syncthreads();
    }

#pragma unroll
    for (int mt = 0; mt < 4; mt++)
#pragma unroll
        for (int nt = 0; nt < 4; nt++)
#pragma unroll
            for (int e = 0; e < 4; e++) {
                int rowg = m0 + wm0 + mt * 16 + g + ((e >= 2) ? 8 : 0);
                int colg = n0 + wn0 + nt * 8 + 2 * q + (e & 1);
                out[(size_t)rowg * N + colg] = acc[mt][nt][e] + bias[colg];
            }
}

// ===========================================================================
// Flash attention — R3 verbatim EXCEPT: Q fragments live in registers,
// converted once at entry (identical values to R3's per-block recompute).
// K/V loader, strides (104/104/72), sync structure unchanged from R3.
// ===========================================================================
#define KHI_OFF 0                          // Khi[64][104]
#define KLO_OFF (64 * 104)                 // Klo[64][104]
#define VS_OFF  (2 * 64 * 104)             // Vs [64][104]
#define PS_OFF  (3 * 64 * 104)             // Ps [128][72]
#define ATT_SMEM_FLOATS (PS_OFF + 128 * 72)
#define ATT_SMEM_BYTES  (ATT_SMEM_FLOATS * 4)

__global__ __launch_bounds__(256, 1)
void attn_kernel(const float* __restrict__ gq, const float* __restrict__ gk,
                 const float* __restrict__ gv, const float* __restrict__ gr,
                 float* __restrict__ gatt)
{
    extern __shared__ float sm[];
    float* Khi = sm + KHI_OFF;
    float* Klo = sm + KLO_OFF;
    float* Vs  = sm + VS_OFF;
    float* Ps  = sm + PS_OFF;

    const int tid  = threadIdx.x;
    const int warp = tid >> 5;
    const int lane = tid & 31;
    const int g = lane >> 2, q = lane & 3;
    const int qr0 = warp * 16;

    const int bh = blockIdx.y;
    const int qb = blockIdx.x;
    const size_t base = (size_t)bh * SEQ * HD;

    // ---- Q fragments -> registers, hi/lo split ONCE ----
    const float* qp = gq + base + (size_t)(qb * 128 + qr0) * HD;
    uint32_t qahi[12][4], qalo[12][4];
#pragma unroll
    for (int ks = 0; ks < 12; ks++) {
        int kc = ks * 8;
        float a0 = qp[g * HD + kc + q];
        float a1 = qp[(g + 8) * HD + kc + q];
        float a2 = qp[g * HD + kc + q + 4];
        float a3 = qp[(g + 8) * HD + kc + q + 4];
        qahi[ks][0] = f2tf(a0); qalo[ks][0] = f2tf(a0 - __uint_as_float(qahi[ks][0]));
        qahi[ks][1] = f2tf(a1); qalo[ks][1] = f2tf(a1 - __uint_as_float(qahi[ks][1]));
        qahi[ks][2] = f2tf(a2); qalo[ks][2] = f2tf(a2 - __uint_as_float(qahi[ks][2]));
        qahi[ks][3] = f2tf(a3); qalo[ks][3] = f2tf(a3 - __uint_as_float(qahi[ks][3]));
    }

    float o[12][4];
    float m_a = -1e30f, m_b = -1e30f, l_a = 0.f, l_b = 0.f;
#pragma unroll
    for (int nt = 0; nt < 12; nt++)
#pragma unroll
        for (int e = 0; e < 4; e++) o[nt][e] = 0.f;

    for (int kb = 0; kb < SEQ / 64; kb++) {
        __syncthreads();                       // prev K/V/P fully consumed
        const float* kptr = gk + base + (size_t)kb * 64 * HD;
        const float* vptr = gv + base + (size_t)kb * 64 * HD;
#pragma unroll
        for (int i = 0; i < 6; i++) {
            int u = i * 256 + tid;             // 1536 float4s
            int row = u / 24, c4 = u % 24;
            float4 kv = *(const float4*)(kptr + row * HD + c4 * 4);
            float4 vv = *(const float4*)(vptr + row * HD + c4 * 4);
            float4 khi4 = make_float4(tfr(kv.x), tfr(kv.y), tfr(kv.z), tfr(kv.w));
            float4 klo4 = make_float4(tfr(kv.x - khi4.x), tfr(kv.y - khi4.y),
                                      tfr(kv.z - khi4.z), tfr(kv.w - khi4.w));
            *(float4*)(Khi + row * 104 + c4 * 4) = khi4;
            *(float4*)(Klo + row * 104 + c4 * 4) = klo4;
            *(float4*)(Vs + row * 104 + c4 * 4) =
                make_float4(tfr(vv.x), tfr(vv.y), tfr(vv.z), tfr(vv.w));
        }
        __syncthreads();

        // ---- S = Q K^T (compensated tf32) ----
        float s_[8][4];
#pragma unroll
        for (int nt = 0; nt < 8; nt++)
#pragma unroll
            for (int e = 0; e < 4; e++) s_[nt][e] = 0.f;

#pragma unroll
        for (int ks = 0; ks < 12; ks++) {
            int kc = ks * 8;
#pragma unroll
            for (int nt = 0; nt < 8; nt++) {
                int nrow = nt * 8 + g;
                uint32_t bh0 = __float_as_uint(Khi[nrow * 104 + kc + q]);
                uint32_t bh1 = __float_as_uint(Khi[nrow * 104 + kc + q + 4]);
                uint32_t bl0 = __float_as_uint(Klo[nrow * 104 + kc + q]);
                uint32_t bl1 = __float_as_uint(Klo[nrow * 104 + kc + q + 4]);
                mma8(s_[nt], qahi[ks][0], qahi[ks][1], qahi[ks][2], qahi[ks][3], bh0, bh1);
                mma8(s_[nt], qalo[ks][0], qalo[ks][1], qalo[ks][2], qalo[ks][3], bh0, bh1);
                mma8(s_[nt], qahi[ks][0], qahi[ks][1], qahi[ks][2], qahi[ks][3], bl0, bl1);
            }
        }

        // ---- online softmax (intra-warp; rows g and g+8) ----
        float mx_a = -1e30f, mx_b = -1e30f;
#pragma unroll
        for (int nt = 0; nt < 8; nt++) {
            mx_a = fmaxf(mx_a, fmaxf(s_[nt][0], s_[nt][1]));
            mx_b = fmaxf(mx_b, fmaxf(s_[nt][2], s_[nt][3]));
        }
        mx_a = fmaxf(mx_a, __shfl_xor_sync(0xffffffffu, mx_a, 1));
        mx_a = fmaxf(mx_a, __shfl_xor_sync(0xffffffffu, mx_a, 2));
        mx_b = fmaxf(mx_b, __shfl_xor_sync(0xffffffffu, mx_b, 1));
        mx_b = fmaxf(mx_b, __shfl_xor_sync(0xffffffffu, mx_b, 2));
        float nm_a = fmaxf(m_a, mx_a), nm_b = fmaxf(m_b, mx_b);
        float sc_a = __expf(m_a - nm_a), sc_b = __expf(m_b - nm_b);
        m_a = nm_a; m_b = nm_b;

        float sum_a = 0.f, sum_b = 0.f;
#pragma unroll
        for (int nt = 0; nt < 8; nt++) {
            float p0 = __expf(s_[nt][0] - nm_a);
            float p1 = __expf(s_[nt][1] - nm_a);
            float p2 = __expf(s_[nt][2] - nm_b);
            float p3 = __expf(s_[nt][3] - nm_b);
            sum_a += p0 + p1; sum_b += p2 + p3;
            int col = nt * 8 + 2 * q;
            Ps[(qr0 + g) * 72 + col]         = tfr(p0);
            Ps[(qr0 + g) * 72 + col + 1]     = tfr(p1);
            Ps[(qr0 + g + 8) * 72 + col]     = tfr(p2);
            Ps[(qr0 + g + 8) * 72 + col + 1] = tfr(p3);
        }
        sum_a += __shfl_xor_sync(0xffffffffu, sum_a, 1);
        sum_a += __shfl_xor_sync(0xffffffffu, sum_a, 2);
        sum_b += __shfl_xor_sync(0xffffffffu, sum_b, 1);
        sum_b += __shfl_xor_sync(0xffffffffu, sum_b, 2);
        l_a = l_a * sc_a + sum_a;
        l_b = l_b * sc_b + sum_b;
#pragma unroll
        for (int nt = 0; nt < 12; nt++) {
            o[nt][0] *= sc_a; o[nt][1] *= sc_a;
            o[nt][2] *= sc_b; o[nt][3] *= sc_b;
        }
        __syncwarp();                          // Ps (own rows) visible in-warp

        // ---- O += P V (plain tf32) ----
#pragma unroll
        for (int ks = 0; ks < 8; ks++) {
            int kc = ks * 8;
            uint32_t pa0 = __float_as_uint(Ps[(qr0 + g) * 72 + kc + q]);
            uint32_t pa1 = __float_as_uint(Ps[(qr0 + g + 8) * 72 + kc + q]);
            uint32_t pa2 = __float_as_uint(Ps[(qr0 + g) * 72 + kc + q + 4]);
            uint32_t pa3 = __float_as_uint(Ps[(qr0 + g + 8) * 72 + kc + q + 4]);
#pragma unroll
            for (int nt = 0; nt < 12; nt++) {
                uint32_t vb0 = __float_as_uint(Vs[(kc + q) * 104 + nt * 8 + g]);
                uint32_t vb1 = __float_as_uint(Vs[(kc + q + 4) * 104 + nt * 8 + g]);
                mma8(o[nt], pa0, pa1, pa2, pa3, vb0, vb1);
            }
        }
        __syncwarp();
    }

    // ---- epilogue: /l, *1/sqrt(768), gate r, store (b, n, h*96+d) ----
    const float inv_sqrt_emb = 0.03608439182435161f;
    const int b_ = bh >> 3, h = bh & 7;
    const float li_a = inv_sqrt_emb / l_a;
    const float li_b = inv_sqrt_emb / l_b;
    const int n_a = qb * 128 + qr0 + g;
    const int n_b = n_a + 8;
#pragma unroll
    for (int nt = 0; nt < 12; nt++) {
        int d = nt * 8 + 2 * q;
        float ra0 = gr[base + (size_t)n_a * HD + d];
        float ra1 = gr[base + (size_t)n_a * HD + d + 1];
        float rb0 = gr[base + (size_t)n_b * HD + d];
        float rb1 = gr[base + (size_t)n_b * HD + d + 1];
        size_t oa = ((size_t)(b_ * SEQ + n_a)) * EMB + h * HD + d;
        size_t ob = ((size_t)(b_ * SEQ + n_b)) * EMB + h * HD + d;
        gatt[oa]     = o[nt][0] * li_a * ra0;
        gatt[oa + 1] = o[nt][1] * li_a * ra1;
        gatt[ob]     = o[nt][2] * li_b * rb0;
        gatt[ob + 1] = o[nt][3] * li_b * rb1;
    }
}

// ===========================================================================
extern "C" void kernel_launch(void* const* d_in, const int* in_sizes, int n_in,
                              void* d_out, int out_size)
{
    const float* x      = (const float*)d_in[0];
    const float* w_qkvr = (const float*)d_in[1];
    const float* b_qkvr = (const float*)d_in[2];
    const float* w_proj = (const float*)d_in[3];
    const float* b_proj = (const float*)d_in[4];
    float* out = (float*)d_out;

    cudaFuncSetAttribute(attn_kernel,
                         cudaFuncAttributeMaxDynamicSharedMemorySize,
                         ATT_SMEM_BYTES);

    float *xhi, *xlo, *whi, *wlo, *gq, *gk, *gv, *gr, *gatt;
    cudaGetSymbolAddress((void**)&xhi, g_xhi);
    cudaGetSymbolAddress((void**)&xlo, g_xlo);
    cudaGetSymbolAddress((void**)&whi, g_whi);
    cudaGetSymbolAddress((void**)&wlo, g_wlo);
    cudaGetSymbolAddress((void**)&gq, g_q);
    cudaGetSymbolAddress((void**)&gk, g_k);
    cudaGetSymbolAddress((void**)&gv, g_v);
    cudaGetSymbolAddress((void**)&gr, g_r);
    cudaGetSymbolAddress((void**)&gatt, g_att);

    split_kernel<<<MROWS * EMB / 4 / 256, 256>>>(x, xhi, xlo, MROWS * EMB / 4);
    split_kernel<<<EMB * QKVN / 4 / 256, 256>>>(w_qkvr, whi, wlo, EMB * QKVN / 4);

    gemm_qkv<<<dim3(QKVN / 128, MROWS / 128), 256>>>(xhi, xlo, whi, wlo, b_qkvr);
    attn_kernel<<<dim3(SEQ / 128, BHTOT), 256, ATT_SMEM_BYTES>>>(
        gq, gk, gv, gr, gatt);
    gemm_proj<<<dim3(EMB / 128, MROWS / 128), 256>>>(gatt, w_proj, b_proj, out, EMB);
}

// round 8
// speedup vs baseline: 1.0584x; 1.0417x over previous
#include <cuda_runtime.h>
#include <cstdint>

#define EMB   768
#define NHEAD 8
#define HD    96
#define BATCH 2
#define SEQ   4096
#define MROWS (BATCH * SEQ)          // 8192
#define QKVN  (4 * EMB)              // 3072
#define BHTOT (BATCH * NHEAD)        // 16

// ---------------- scratch (static device globals; no allocs) ---------------
__device__ float g_xhl[MROWS * EMB * 2];     // interleaved (hi,lo)
__device__ float g_whl[EMB * QKVN * 2];      // interleaved (hi,lo)
__device__ float g_q[BHTOT * SEQ * HD];
__device__ float g_k[BHTOT * SEQ * HD];
__device__ float g_v[BHTOT * SEQ * HD];
__device__ float g_r[BHTOT * SEQ * HD];
__device__ float g_att[MROWS * EMB];

// ---------------- tf32 helpers ---------------------------------------------
__device__ __forceinline__ uint32_t f2tf(float x) {
    uint32_t r;
    asm("cvt.rna.tf32.f32 %0, %1;" : "=r"(r) : "f"(x));
    return r;
}
__device__ __forceinline__ float tfr(float x) { return __uint_as_float(f2tf(x)); }

__device__ __forceinline__ void mma8(float* d,
                                     uint32_t a0, uint32_t a1, uint32_t a2, uint32_t a3,
                                     uint32_t b0, uint32_t b1) {
    asm volatile(
        "mma.sync.aligned.m16n8k8.row.col.f32.tf32.tf32.f32 "
        "{%0,%1,%2,%3}, {%4,%5,%6,%7}, {%8,%9}, {%0,%1,%2,%3};"
        : "+f"(d[0]), "+f"(d[1]), "+f"(d[2]), "+f"(d[3])
        : "r"(a0), "r"(a1), "r"(a2), "r"(a3), "r"(b0), "r"(b1));
}

__device__ __forceinline__ void cp16(float* dst_smem, const float* src) {
    uint32_t d = (uint32_t)__cvta_generic_to_shared(dst_smem);
    asm volatile("cp.async.cg.shared.global [%0], [%1], 16;\n" :: "r"(d), "l"(src));
}
__device__ __forceinline__ void cp_commit() {
    asm volatile("cp.async.commit_group;\n");
}
template <int N>
__device__ __forceinline__ void cp_wait() {
    asm volatile("cp.async.wait_group %0;\n" :: "n"(N));
}

// ---------------- pre-split (interleaved hi,lo) ----------------------------
__global__ void split_il(const float* __restrict__ in, float* __restrict__ hl, int n4) {
    int i = blockIdx.x * blockDim.x + threadIdx.x;
    if (i >= n4) return;
    float4 v = ((const float4*)in)[i];
    float hx = tfr(v.x), hy = tfr(v.y), hz = tfr(v.z), hw = tfr(v.w);
    ((float4*)hl)[i * 2]     = make_float4(hx, tfr(v.x - hx), hy, tfr(v.y - hy));
    ((float4*)hl)[i * 2 + 1] = make_float4(hz, tfr(v.z - hz), hw, tfr(v.w - hw));
}

// ===========================================================================
// QKV GEMM: interleaved (hi,lo) operands, cp.async 2-stage pipeline,
// BM=128 BN=128 BK=16, 256 threads (2x4 warps, 64x32 warp tile).
// A smem [m][k*2] stride 40; B smem [k][n*2] stride 264. All frag LDS are .64.
// Epilogue (bias + qkvr scatter) identical to R5.
// ===========================================================================
#define QA_ST 40
#define QB_ST 264
#define QA_SZ (128 * QA_ST)    // 5120
#define QB_SZ (16 * QB_ST)     // 4224
#define QKV_SMEM_BYTES ((2 * QA_SZ + 2 * QB_SZ) * 4)   // 74752

__global__ __launch_bounds__(256, 1)
void gemm_qkv(const float* __restrict__ Axl, const float* __restrict__ Bxl,
              const float* __restrict__ bias)
{
    extern __shared__ float smq[];
    float* sA = smq;                  // [2][QA_SZ]
    float* sB = smq + 2 * QA_SZ;      // [2][QB_SZ]

    const int K  = EMB, N = QKVN;
    const int m0 = blockIdx.y * 128;
    const int n0 = blockIdx.x * 128;
    const int tid  = threadIdx.x;
    const int warp = tid >> 5;
    const int lane = tid & 31;
    const int g = lane >> 2, q = lane & 3;
    const int wm0 = (warp >> 2) * 64;
    const int wn0 = (warp & 3) * 32;

    float acc[4][4][4];
#pragma unroll
    for (int i = 0; i < 4; i++)
#pragma unroll
        for (int j = 0; j < 4; j++)
#pragma unroll
            for (int e = 0; e < 4; e++) acc[i][j][e] = 0.f;

    auto issue = [&](int k0, int s) {
        float* Ad = sA + s * QA_SZ;
        float* Bd = sB + s * QB_SZ;
#pragma unroll
        for (int it = 0; it < 4; it++) {
            int u = it * 256 + tid;                 // [0,1024)
            int arow = u >> 3, ac = (u & 7) * 4;    // 128 rows x 8 chunks (32 floats/row)
            cp16(Ad + arow * QA_ST + ac,
                 Axl + ((size_t)(m0 + arow) * K + k0) * 2 + ac);
            int brow = u >> 6, bc = (u & 63) * 4;   // 16 rows x 64 chunks (256 floats/row)
            cp16(Bd + brow * QB_ST + bc,
                 Bxl + ((size_t)(k0 + brow) * N + n0) * 2 + bc);
        }
    };

    issue(0, 0);
    cp_commit();

    const int NITER = K / 16;                       // 48
    for (int i = 0; i < NITER; i++) {
        int s = i & 1;
        if (i + 1 < NITER) {
            issue((i + 1) * 16, s ^ 1);
            cp_commit();
            cp_wait<1>();
        } else {
            cp_wait<0>();
        }
        __syncthreads();

        const float* Ah = sA + s * QA_SZ;
        const float* Bh = sB + s * QB_SZ;
#pragma unroll
        for (int kk = 0; kk < 16; kk += 8) {
            uint32_t ahi[4][4], alo[4][4];
#pragma unroll
            for (int mt = 0; mt < 4; mt++) {
                int mrow = wm0 + mt * 16 + g;
                float2 x0 = *(const float2*)(Ah + mrow * QA_ST + (kk + q) * 2);
                float2 x1 = *(const float2*)(Ah + (mrow + 8) * QA_ST + (kk + q) * 2);
                float2 x2 = *(const float2*)(Ah + mrow * QA_ST + (kk + q + 4) * 2);
                float2 x3 = *(const float2*)(Ah + (mrow + 8) * QA_ST + (kk + q + 4) * 2);
                ahi[mt][0] = __float_as_uint(x0.x); alo[mt][0] = __float_as_uint(x0.y);
                ahi[mt][1] = __float_as_uint(x1.x); alo[mt][1] = __float_as_uint(x1.y);
                ahi[mt][2] = __float_as_uint(x2.x); alo[mt][2] = __float_as_uint(x2.y);
                ahi[mt][3] = __float_as_uint(x3.x); alo[mt][3] = __float_as_uint(x3.y);
            }
            uint32_t bhi[4][2], blo[4][2];
#pragma unroll
            for (int nt = 0; nt < 4; nt++) {
                int ncol = wn0 + nt * 8 + g;
                float2 b0 = *(const float2*)(Bh + (kk + q) * QB_ST + ncol * 2);
                float2 b1 = *(const float2*)(Bh + (kk + q + 4) * QB_ST + ncol * 2);
                bhi[nt][0] = __float_as_uint(b0.x); blo[nt][0] = __float_as_uint(b0.y);
                bhi[nt][1] = __float_as_uint(b1.x); blo[nt][1] = __float_as_uint(b1.y);
            }
#pragma unroll
            for (int mt = 0; mt < 4; mt++)
#pragma unroll
                for (int nt = 0; nt < 4; nt++) {
                    mma8(acc[mt][nt], ahi[mt][0], ahi[mt][1], ahi[mt][2], ahi[mt][3],
                         bhi[nt][0], bhi[nt][1]);
                    mma8(acc[mt][nt], alo[mt][0], alo[mt][1], alo[mt][2], alo[mt][3],
                         bhi[nt][0], bhi[nt][1]);
                    mma8(acc[mt][nt], ahi[mt][0], ahi[mt][1], ahi[mt][2], ahi[mt][3],
                         blo[nt][0], blo[nt][1]);
                }
        }
        __syncthreads();
    }

    // epilogue — R5 verbatim (bias + raw q/k/v/r scatter)
#pragma unroll
    for (int mt = 0; mt < 4; mt++)
#pragma unroll
        for (int nt = 0; nt < 4; nt++)
#pragma unroll
            for (int e = 0; e < 4; e++) {
                int rowg = m0 + wm0 + mt * 16 + g + ((e >= 2) ? 8 : 0);
                int colg = n0 + wn0 + nt * 8 + 2 * q + (e & 1);
                float val = acc[mt][nt][e] + bias[colg];
                int b_   = rowg >> 12;
                int n    = rowg & 4095;
                int qk   = colg & 3;
                int rest = colg >> 2;
                int d    = rest % 96;
                int h    = rest / 96;
                size_t dst = ((size_t)(b_ * NHEAD + h) * SEQ + n) * HD + d;
                float* t = (qk == 0) ? g_q : (qk == 1) ? g_k : (qk == 2) ? g_v : g_r;
                t[dst] = val;
            }
}

// ===========================================================================
// Out-projection GEMM — verbatim R5 (in-loop cvt, plain tf32).
// ===========================================================================
__global__ __launch_bounds__(256, 1)
void gemm_proj(const float* __restrict__ A, const float* __restrict__ B,
               const float* __restrict__ bias, float* __restrict__ out, int N)
{
    __shared__ float As[16 * 136];
    __shared__ float Bs[16 * 136];

    const int K  = EMB;
    const int m0 = blockIdx.y * 128;
    const int n0 = blockIdx.x * 128;
    const int tid  = threadIdx.x;
    const int warp = tid >> 5;
    const int lane = tid & 31;
    const int g = lane >> 2, q = lane & 3;
    const int wm0 = (warp >> 2) * 64;
    const int wn0 = (warp & 3) * 32;

    float acc[4][4][4];
#pragma unroll
    for (int i = 0; i < 4; i++)
#pragma unroll
        for (int j = 0; j < 4; j++)
#pragma unroll
            for (int e = 0; e < 4; e++) acc[i][j][e] = 0.f;

    for (int k0 = 0; k0 < K; k0 += 16) {
#pragma unroll
        for (int it = 0; it < 2; it++) {
            int u = it * 256 + tid;
            int arow = u >> 2, ac4 = u & 3;
            float4 av = *(const float4*)(A + (size_t)(m0 + arow) * K + k0 + ac4 * 4);
            As[(ac4 * 4 + 0) * 136 + arow] = av.x;
            As[(ac4 * 4 + 1) * 136 + arow] = av.y;
            As[(ac4 * 4 + 2) * 136 + arow] = av.z;
            As[(ac4 * 4 + 3) * 136 + arow] = av.w;
            int brow = u >> 5, bc4 = u & 31;
            *(float4*)(&Bs[brow * 136 + bc4 * 4]) =
                *(const float4*)(B + (size_t)(k0 + brow) * N + n0 + bc4 * 4);
        }
        __syncthreads();

#pragma unroll
        for (int kk = 0; kk < 16; kk += 8) {
            uint32_t ahi[4][4];
#pragma unroll
            for (int mt = 0; mt < 4; mt++) {
                int mrow = wm0 + mt * 16 + g;
                ahi[mt][0] = f2tf(As[(kk + q) * 136 + mrow]);
                ahi[mt][1] = f2tf(As[(kk + q) * 136 + mrow + 8]);
                ahi[mt][2] = f2tf(As[(kk + q + 4) * 136 + mrow]);
                ahi[mt][3] = f2tf(As[(kk + q + 4) * 136 + mrow + 8]);
            }
            uint32_t bhi[4][2];
#pragma unroll
            for (int nt = 0; nt < 4; nt++) {
                int ncol = wn0 + nt * 8 + g;
                bhi[nt][0] = f2tf(Bs[(kk + q) * 136 + ncol]);
                bhi[nt][1] = f2tf(Bs[(kk + q + 4) * 136 + ncol]);
            }
#pragma unroll
            for (int mt = 0; mt < 4; mt++)
#pragma unroll
                for (int nt = 0; nt < 4; nt++)
                    mma8(acc[mt][nt], ahi[mt][0], ahi[mt][1], ahi[mt][2], ahi[mt][3],
                         bhi[nt][0], bhi[nt][1]);
        }
        __syncthreads();
    }

#pragma unroll
    for (int mt = 0; mt < 4; mt++)
#pragma unroll
        for (int nt = 0; nt < 4; nt++)
#pragma unroll
            for (int e = 0; e < 4; e++) {
                int rowg = m0 + wm0 + mt * 16 + g + ((e >= 2) ? 8 : 0);
                int colg = n0 + wn0 + nt * 8 + 2 * q + (e & 1);
                out[(size_t)rowg * N + colg] = acc[mt][nt][e] + bias[colg];
            }
}

// ===========================================================================
// Flash attention — pair-interleaved smem layouts, all hot LDS/STS are 64-bit.
//   Khl[key][d*2+{hi,lo}]          stride 200   (QK^T: 2 LDS.64 / (ks,nt))
//   Vp [rp][d*2+{key,key+4}]       stride 200   (PV:   1 LDS.64 / (ks,nt))
//   Pp per warp [col][g*2+{g,g+8}] stride 24    (2 LDS.64 + 2 STS.64)
// Values, rounding, accumulation order identical to R5.
// ===========================================================================
#define KST2 200
#define VST2 200
#define PST2 24
#define KHL_SZ (64 * KST2)          // 12800
#define VP_SZ  (32 * VST2)          // 6400
#define PP_SZ  (8 * 64 * PST2)      // 12288
#define ATT_SMEM_FLOATS (KHL_SZ + VP_SZ + PP_SZ)   // 31488
#define ATT_SMEM_BYTES  (ATT_SMEM_FLOATS * 4)      // 125952

__global__ __launch_bounds__(256, 1)
void attn_kernel(const float* __restrict__ gq, const float* __restrict__ gk,
                 const float* __restrict__ gv, const float* __restrict__ gr,
                 float* __restrict__ gatt)
{
    extern __shared__ float sm[];
    float* Khl = sm;
    float* Vp  = sm + KHL_SZ;
    float* Pp  = sm + KHL_SZ + VP_SZ;

    const int tid  = threadIdx.x;
    const int warp = tid >> 5;
    const int lane = tid & 31;
    const int g = lane >> 2, q = lane & 3;
    const int qr0 = warp * 16;
    float* Pw = Pp + warp * (64 * PST2);

    const int bh = blockIdx.y;
    const int qb = blockIdx.x;
    const size_t base = (size_t)bh * SEQ * HD;

    // ---- Q fragments -> registers, hi/lo split ONCE (identical to R5) ----
    const float* qp = gq + base + (size_t)(qb * 128 + qr0) * HD;
    uint32_t qahi[12][4], qalo[12][4];
#pragma unroll
    for (int ks = 0; ks < 12; ks++) {
        int kc = ks * 8;
        float a0 = qp[g * HD + kc + q];
        float a1 = qp[(g + 8) * HD + kc + q];
        float a2 = qp[g * HD + kc + q + 4];
        float a3 = qp[(g + 8) * HD + kc + q + 4];
        qahi[ks][0] = f2tf(a0); qalo[ks][0] = f2tf(a0 - __uint_as_float(qahi[ks][0]));
        qahi[ks][1] = f2tf(a1); qalo[ks][1] = f2tf(a1 - __uint_as_float(qahi[ks][1]));
        qahi[ks][2] = f2tf(a2); qalo[ks][2] = f2tf(a2 - __uint_as_float(qahi[ks][2]));
        qahi[ks][3] = f2tf(a3); qalo[ks][3] = f2tf(a3 - __uint_as_float(qahi[ks][3]));
    }

    float o[12][4];
    float m_a = -1e30f, m_b = -1e30f, l_a = 0.f, l_b = 0.f;
#pragma unroll
    for (int nt = 0; nt < 12; nt++)
#pragma unroll
        for (int e = 0; e < 4; e++) o[nt][e] = 0.f;

    for (int kb = 0; kb < SEQ / 64; kb++) {
        __syncthreads();                       // prev K/V fully consumed
        const float* kptr = gk + base + (size_t)kb * 64 * HD;
        const float* vptr = gv + base + (size_t)kb * 64 * HD;
        // K: 64 rows x 24 chunks, (hi,lo) interleaved
#pragma unroll
        for (int i = 0; i < 6; i++) {
            int u = i * 256 + tid;
            int row = u / 24, c4 = u % 24;
            float4 kv = *(const float4*)(kptr + row * HD + c4 * 4);
            float hx = tfr(kv.x), hy = tfr(kv.y), hz = tfr(kv.z), hw = tfr(kv.w);
            float* kd = Khl + row * KST2 + c4 * 8;
            *(float4*)(kd)     = make_float4(hx, tfr(kv.x - hx), hy, tfr(kv.y - hy));
            *(float4*)(kd + 4) = make_float4(hz, tfr(kv.z - hz), hw, tfr(kv.w - hw));
        }
        // V: 32 row-pairs x 24 chunks, keys (r, r+4) interleaved
#pragma unroll
        for (int i = 0; i < 3; i++) {
            int u = i * 256 + tid;
            int rp = u / 24, c4 = u % 24;
            int key_a = (rp >> 2) * 8 + (rp & 3);
            const float* va = vptr + (size_t)key_a * HD + c4 * 4;
            float4 a = *(const float4*)va;
            float4 b = *(const float4*)(va + 4 * HD);
            float* vd = Vp + rp * VST2 + c4 * 8;
            *(float4*)(vd)     = make_float4(tfr(a.x), tfr(b.x), tfr(a.y), tfr(b.y));
            *(float4*)(vd + 4) = make_float4(tfr(a.z), tfr(b.z), tfr(a.w), tfr(b.w));
        }
        __syncthreads();

        // ---- S = Q K^T (compensated tf32) ----
        float s_[8][4];
#pragma unroll
        for (int nt = 0; nt < 8; nt++)
#pragma unroll
            for (int e = 0; e < 4; e++) s_[nt][e] = 0.f;

#pragma unroll
        for (int ks = 0; ks < 12; ks++) {
            int kc = ks * 8;
#pragma unroll
            for (int nt = 0; nt < 8; nt++) {
                const float* kr = Khl + (nt * 8 + g) * KST2;
                float2 hl0 = *(const float2*)(kr + (kc + q) * 2);
                float2 hl1 = *(const float2*)(kr + (kc + q + 4) * 2);
                uint32_t bh0 = __float_as_uint(hl0.x), bl0 = __float_as_uint(hl0.y);
                uint32_t bh1 = __float_as_uint(hl1.x), bl1 = __float_as_uint(hl1.y);
                mma8(s_[nt], qahi[ks][0], qahi[ks][1], qahi[ks][2], qahi[ks][3], bh0, bh1);
                mma8(s_[nt], qalo[ks][0], qalo[ks][1], qalo[ks][2], qalo[ks][3], bh0, bh1);
                mma8(s_[nt], qahi[ks][0], qahi[ks][1], qahi[ks][2], qahi[ks][3], bl0, bl1);
            }
        }

        // ---- online softmax (intra-warp; rows g and g+8) ----
        float mx_a = -1e30f, mx_b = -1e30f;
#pragma unroll
        for (int nt = 0; nt < 8; nt++) {
            mx_a = fmaxf(mx_a, fmaxf(s_[nt][0], s_[nt][1]));
            mx_b = fmaxf(mx_b, fmaxf(s_[nt][2], s_[nt][3]));
        }
        mx_a = fmaxf(mx_a, __shfl_xor_sync(0xffffffffu, mx_a, 1));
        mx_a = fmaxf(mx_a, __shfl_xor_sync(0xffffffffu, mx_a, 2));
        mx_b = fmaxf(mx_b, __shfl_xor_sync(0xffffffffu, mx_b, 1));
        mx_b = fmaxf(mx_b, __shfl_xor_sync(0xffffffffu, mx_b, 2));
        float nm_a = fmaxf(m_a, mx_a), nm_b = fmaxf(m_b, mx_b);
        float sc_a = __expf(m_a - nm_a), sc_b = __expf(m_b - nm_b);
        m_a = nm_a; m_b = nm_b;

        float sum_a = 0.f, sum_b = 0.f;
#pragma unroll
        for (int nt = 0; nt < 8; nt++) {
            float p0 = __expf(s_[nt][0] - nm_a);
            float p1 = __expf(s_[nt][1] - nm_a);
            float p2 = __expf(s_[nt][2] - nm_b);
            float p3 = __expf(s_[nt][3] - nm_b);
            sum_a += p0 + p1; sum_b += p2 + p3;
            int col = nt * 8 + 2 * q;
            *(float2*)(Pw + col * PST2 + g * 2)       = make_float2(tfr(p0), tfr(p2));
            *(float2*)(Pw + (col + 1) * PST2 + g * 2) = make_float2(tfr(p1), tfr(p3));
        }
        sum_a += __shfl_xor_sync(0xffffffffu, sum_a, 1);
        sum_a += __shfl_xor_sync(0xffffffffu, sum_a, 2);
        sum_b += __shfl_xor_sync(0xffffffffu, sum_b, 1);
        sum_b += __shfl_xor_sync(0xffffffffu, sum_b, 2);
        l_a = l_a * sc_a + sum_a;
        l_b = l_b * sc_b + sum_b;
#pragma unroll
        for (int nt = 0; nt < 12; nt++) {
            o[nt][0] *= sc_a; o[nt][1] *= sc_a;
            o[nt][2] *= sc_b; o[nt][3] *= sc_b;
        }
        __syncwarp();                          // Pw (own warp's rows) visible

        // ---- O += P V (plain tf32) ----
#pragma unroll
        for (int ks = 0; ks < 8; ks++) {
            int kc = ks * 8;
            float2 pA = *(const float2*)(Pw + (kc + q) * PST2 + g * 2);     // pa0,pa1
            float2 pB = *(const float2*)(Pw + (kc + q + 4) * PST2 + g * 2); // pa2,pa3
            uint32_t pa0 = __float_as_uint(pA.x), pa1 = __float_as_uint(pA.y);
            uint32_t pa2 = __float_as_uint(pB.x), pa3 = __float_as_uint(pB.y);
            const float* vr = Vp + (ks * 4 + q) * VST2;
#pragma unroll
            for (int nt = 0; nt < 12; nt++) {
                float2 v2 = *(const float2*)(vr + (nt * 8 + g) * 2);        // vb0,vb1
                mma8(o[nt], pa0, pa1, pa2, pa3,
                     __float_as_uint(v2.x), __float_as_uint(v2.y));
            }
        }
        __syncwarp();
    }

    // ---- epilogue: /l, *1/sqrt(768), gate r, store (b, n, h*96+d) ----
    const float inv_sqrt_emb = 0.03608439182435161f;
    const int b_ = bh >> 3, h = bh & 7;
    const float li_a = inv_sqrt_emb / l_a;
    const float li_b = inv_sqrt_emb / l_b;
    const int n_a = qb * 128 + qr0 + g;
    const int n_b = n_a + 8;
#pragma unroll
    for (int nt = 0; nt < 12; nt++) {
        int d = nt * 8 + 2 * q;
        float ra0 = gr[base + (size_t)n_a * HD + d];
        float ra1 = gr[base + (size_t)n_a * HD + d + 1];
        float rb0 = gr[base + (size_t)n_b * HD + d];
        float rb1 = gr[base + (size_t)n_b * HD + d + 1];
        size_t oa = ((size_t)(b_ * SEQ + n_a)) * EMB + h * HD + d;
        size_t ob = ((size_t)(b_ * SEQ + n_b)) * EMB + h * HD + d;
        gatt[oa]     = o[nt][0] * li_a * ra0;
        gatt[oa + 1] = o[nt][1] * li_a * ra1;
        gatt[ob]     = o[nt][2] * li_b * rb0;
        gatt[ob + 1] = o[nt][3] * li_b * rb1;
    }
}

// ===========================================================================
extern "C" void kernel_launch(void* const* d_in, const int* in_sizes, int n_in,
                              void* d_out, int out_size)
{
    const float* x      = (const float*)d_in[0];
    const float* w_qkvr = (const float*)d_in[1];
    const float* b_qkvr = (const float*)d_in[2];
    const float* w_proj = (const float*)d_in[3];
    const float* b_proj = (const float*)d_in[4];
    float* out = (float*)d_out;

    cudaFuncSetAttribute(gemm_qkv,
                         cudaFuncAttributeMaxDynamicSharedMemorySize, QKV_SMEM_BYTES);
    cudaFuncSetAttribute(attn_kernel,
                         cudaFuncAttributeMaxDynamicSharedMemorySize, ATT_SMEM_BYTES);

    float *xhl, *whl, *gq, *gk, *gv, *gr, *gatt;
    cudaGetSymbolAddress((void**)&xhl, g_xhl);
    cudaGetSymbolAddress((void**)&whl, g_whl);
    cudaGetSymbolAddress((void**)&gq, g_q);
    cudaGetSymbolAddress((void**)&gk, g_k);
    cudaGetSymbolAddress((void**)&gv, g_v);
    cudaGetSymbolAddress((void**)&gr, g_r);
    cudaGetSymbolAddress((void**)&gatt, g_att);

    split_il<<<MROWS * EMB / 4 / 256, 256>>>(x, xhl, MROWS * EMB / 4);
    split_il<<<EMB * QKVN / 4 / 256, 256>>>(w_qkvr, whl, EMB * QKVN / 4);

    gemm_qkv<<<dim3(QKVN / 128, MROWS / 128), 256, QKV_SMEM_BYTES>>>(
        xhl, whl, b_qkvr);
    attn_kernel<<<dim3(SEQ / 128, BHTOT), 256, ATT_SMEM_BYTES>>>(
        gq, gk, gv, gr, gatt);
    gemm_proj<<<dim3(EMB / 128, MROWS / 128), 256>>>(gatt, w_proj, b_proj, out, EMB);
}

// round 9
// speedup vs baseline: 1.2987x; 1.2271x over previous
#include <cuda_runtime.h>
#include <cuda_fp16.h>
#include <cstdint>

#define EMB   768
#define NHEAD 8
#define HD    96
#define BATCH 2
#define SEQ   4096
#define MROWS (BATCH * SEQ)          // 8192
#define QKVN  (4 * EMB)              // 3072
#define BHTOT (BATCH * NHEAD)        // 16

// ---------------- scratch (static device globals; no allocs) ---------------
__device__ float g_xhl[MROWS * EMB * 2];     // interleaved (hi,lo) tf32
__device__ float g_whl[EMB * QKVN * 2];      // interleaved (hi,lo) tf32
__device__ float g_q[BHTOT * SEQ * HD];
__device__ float g_k[BHTOT * SEQ * HD];
__device__ float g_v[BHTOT * SEQ * HD];
__device__ float g_r[BHTOT * SEQ * HD];
__device__ float g_att[MROWS * EMB];

// ---------------- tf32 helpers (GEMMs, unchanged) ---------------------------
__device__ __forceinline__ uint32_t f2tf(float x) {
    uint32_t r;
    asm("cvt.rna.tf32.f32 %0, %1;" : "=r"(r) : "f"(x));
    return r;
}
__device__ __forceinline__ float tfr(float x) { return __uint_as_float(f2tf(x)); }

__device__ __forceinline__ void mma8(float* d,
                                     uint32_t a0, uint32_t a1, uint32_t a2, uint32_t a3,
                                     uint32_t b0, uint32_t b1) {
    asm volatile(
        "mma.sync.aligned.m16n8k8.row.col.f32.tf32.tf32.f32 "
        "{%0,%1,%2,%3}, {%4,%5,%6,%7}, {%8,%9}, {%0,%1,%2,%3};"
        : "+f"(d[0]), "+f"(d[1]), "+f"(d[2]), "+f"(d[3])
        : "r"(a0), "r"(a1), "r"(a2), "r"(a3), "r"(b0), "r"(b1));
}

// fp16 m16n8k16 mma, fp32 accumulate (attention)
__device__ __forceinline__ void mma16h(float* d,
                                       uint32_t a0, uint32_t a1, uint32_t a2, uint32_t a3,
                                       uint32_t b0, uint32_t b1) {
    asm volatile(
        "mma.sync.aligned.m16n8k16.row.col.f32.f16.f16.f32 "
        "{%0,%1,%2,%3}, {%4,%5,%6,%7}, {%8,%9}, {%0,%1,%2,%3};"
        : "+f"(d[0]), "+f"(d[1]), "+f"(d[2]), "+f"(d[3])
        : "r"(a0), "r"(a1), "r"(a2), "r"(a3), "r"(b0), "r"(b1));
}

__device__ __forceinline__ uint32_t pack_h2(float a, float b) {
    __half2 h = __floats2half2_rn(a, b);     // x=a (low), y=b (high)
    return *reinterpret_cast<uint32_t*>(&h);
}

__device__ __forceinline__ void cp16(float* dst_smem, const float* src) {
    uint32_t d = (uint32_t)__cvta_generic_to_shared(dst_smem);
    asm volatile("cp.async.cg.shared.global [%0], [%1], 16;\n" :: "r"(d), "l"(src));
}
__device__ __forceinline__ void cp_commit() {
    asm volatile("cp.async.commit_group;\n");
}
template <int N>
__device__ __forceinline__ void cp_wait() {
    asm volatile("cp.async.wait_group %0;\n" :: "n"(N));
}

// ---------------- pre-split (interleaved hi,lo) — R8 verbatim ---------------
__global__ void split_il(const float* __restrict__ in, float* __restrict__ hl, int n4) {
    int i = blockIdx.x * blockDim.x + threadIdx.x;
    if (i >= n4) return;
    float4 v = ((const float4*)in)[i];
    float hx = tfr(v.x), hy = tfr(v.y), hz = tfr(v.z), hw = tfr(v.w);
    ((float4*)hl)[i * 2]     = make_float4(hx, tfr(v.x - hx), hy, tfr(v.y - hy));
    ((float4*)hl)[i * 2 + 1] = make_float4(hz, tfr(v.z - hz), hw, tfr(v.w - hw));
}

// ===========================================================================
// QKV GEMM — R8 verbatim (tf32 compensated, cp.async 2-stage).
// ===========================================================================
#define QA_ST 40
#define QB_ST 264
#define QA_SZ (128 * QA_ST)    // 5120
#define QB_SZ (16 * QB_ST)     // 4224
#define QKV_SMEM_BYTES ((2 * QA_SZ + 2 * QB_SZ) * 4)   // 74752

__global__ __launch_bounds__(256, 1)
void gemm_qkv(const float* __restrict__ Axl, const float* __restrict__ Bxl,
              const float* __restrict__ bias)
{
    extern __shared__ float smq[];
    float* sA = smq;
    float* sB = smq + 2 * QA_SZ;

    const int K  = EMB, N = QKVN;
    const int m0 = blockIdx.y * 128;
    const int n0 = blockIdx.x * 128;
    const int tid  = threadIdx.x;
    const int warp = tid >> 5;
    const int lane = tid & 31;
    const int g = lane >> 2, q = lane & 3;
    const int wm0 = (warp >> 2) * 64;
    const int wn0 = (warp & 3) * 32;

    float acc[4][4][4];
#pragma unroll
    for (int i = 0; i < 4; i++)
#pragma unroll
        for (int j = 0; j < 4; j++)
#pragma unroll
            for (int e = 0; e < 4; e++) acc[i][j][e] = 0.f;

    auto issue = [&](int k0, int s) {
        float* Ad = sA + s * QA_SZ;
        float* Bd = sB + s * QB_SZ;
#pragma unroll
        for (int it = 0; it < 4; it++) {
            int u = it * 256 + tid;
            int arow = u >> 3, ac = (u & 7) * 4;
            cp16(Ad + arow * QA_ST + ac,
                 Axl + ((size_t)(m0 + arow) * K + k0) * 2 + ac);
            int brow = u >> 6, bc = (u & 63) * 4;
            cp16(Bd + brow * QB_ST + bc,
                 Bxl + ((size_t)(k0 + brow) * N + n0) * 2 + bc);
        }
    };

    issue(0, 0);
    cp_commit();

    const int NITER = K / 16;
    for (int i = 0; i < NITER; i++) {
        int s = i & 1;
        if (i + 1 < NITER) {
            issue((i + 1) * 16, s ^ 1);
            cp_commit();
            cp_wait<1>();
        } else {
            cp_wait<0>();
        }
        __syncthreads();

        const float* Ah = sA + s * QA_SZ;
        const float* Bh = sB + s * QB_SZ;
#pragma unroll
        for (int kk = 0; kk < 16; kk += 8) {
            uint32_t ahi[4][4], alo[4][4];
#pragma unroll
            for (int mt = 0; mt < 4; mt++) {
                int mrow = wm0 + mt * 16 + g;
                float2 x0 = *(const float2*)(Ah + mrow * QA_ST + (kk + q) * 2);
                float2 x1 = *(const float2*)(Ah + (mrow + 8) * QA_ST + (kk + q) * 2);
                float2 x2 = *(const float2*)(Ah + mrow * QA_ST + (kk + q + 4) * 2);
                float2 x3 = *(const float2*)(Ah + (mrow + 8) * QA_ST + (kk + q + 4) * 2);
                ahi[mt][0] = __float_as_uint(x0.x); alo[mt][0] = __float_as_uint(x0.y);
                ahi[mt][1] = __float_as_uint(x1.x); alo[mt][1] = __float_as_uint(x1.y);
                ahi[mt][2] = __float_as_uint(x2.x); alo[mt][2] = __float_as_uint(x2.y);
                ahi[mt][3] = __float_as_uint(x3.x); alo[mt][3] = __float_as_uint(x3.y);
            }
            uint32_t bhi[4][2], blo[4][2];
#pragma unroll
            for (int nt = 0; nt < 4; nt++) {
                int ncol = wn0 + nt * 8 + g;
                float2 b0 = *(const float2*)(Bh + (kk + q) * QB_ST + ncol * 2);
                float2 b1 = *(const float2*)(Bh + (kk + q + 4) * QB_ST + ncol * 2);
                bhi[nt][0] = __float_as_uint(b0.x); blo[nt][0] = __float_as_uint(b0.y);
                bhi[nt][1] = __float_as_uint(b1.x); blo[nt][1] = __float_as_uint(b1.y);
            }
#pragma unroll
            for (int mt = 0; mt < 4; mt++)
#pragma unroll
                for (int nt = 0; nt < 4; nt++) {
                    mma8(acc[mt][nt], ahi[mt][0], ahi[mt][1], ahi[mt][2], ahi[mt][3],
                         bhi[nt][0], bhi[nt][1]);
                    mma8(acc[mt][nt], alo[mt][0], alo[mt][1], alo[mt][2], alo[mt][3],
                         bhi[nt][0], bhi[nt][1]);
                    mma8(acc[mt][nt], ahi[mt][0], ahi[mt][1], ahi[mt][2], ahi[mt][3],
                         blo[nt][0], blo[nt][1]);
                }
        }
        __syncthreads();
    }

#pragma unroll
    for (int mt = 0; mt < 4; mt++)
#pragma unroll
        for (int nt = 0; nt < 4; nt++)
#pragma unroll
            for (int e = 0; e < 4; e++) {
                int rowg = m0 + wm0 + mt * 16 + g + ((e >= 2) ? 8 : 0);
                int colg = n0 + wn0 + nt * 8 + 2 * q + (e & 1);
                float val = acc[mt][nt][e] + bias[colg];
                int b_   = rowg >> 12;
                int n    = rowg & 4095;
                int qk   = colg & 3;
                int rest = colg >> 2;
                int d    = rest % 96;
                int h    = rest / 96;
                size_t dst = ((size_t)(b_ * NHEAD + h) * SEQ + n) * HD + d;
                float* t = (qk == 0) ? g_q : (qk == 1) ? g_k : (qk == 2) ? g_v : g_r;
                t[dst] = val;
            }
}

// ===========================================================================
// Out-projection GEMM — R8 verbatim.
// ===========================================================================
__global__ __launch_bounds__(256, 1)
void gemm_proj(const float* __restrict__ A, const float* __restrict__ B,
               const float* __restrict__ bias, float* __restrict__ out, int N)
{
    __shared__ float As[16 * 136];
    __shared__ float Bs[16 * 136];

    const int K  = EMB;
    const int m0 = blockIdx.y * 128;
    const int n0 = blockIdx.x * 128;
    const int tid  = threadIdx.x;
    const int warp = tid >> 5;
    const int lane = tid & 31;
    const int g = lane >> 2, q = lane & 3;
    const int wm0 = (warp >> 2) * 64;
    const int wn0 = (warp & 3) * 32;

    float acc[4][4][4];
#pragma unroll
    for (int i = 0; i < 4; i++)
#pragma unroll
        for (int j = 0; j < 4; j++)
#pragma unroll
            for (int e = 0; e < 4; e++) acc[i][j][e] = 0.f;

    for (int k0 = 0; k0 < K; k0 += 16) {
#pragma unroll
        for (int it = 0; it < 2; it++) {
            int u = it * 256 + tid;
            int arow = u >> 2, ac4 = u & 3;
            float4 av = *(const float4*)(A + (size_t)(m0 + arow) * K + k0 + ac4 * 4);
            As[(ac4 * 4 + 0) * 136 + arow] = av.x;
            As[(ac4 * 4 + 1) * 136 + arow] = av.y;
            As[(ac4 * 4 + 2) * 136 + arow] = av.z;
            As[(ac4 * 4 + 3) * 136 + arow] = av.w;
            int brow = u >> 5, bc4 = u & 31;
            *(float4*)(&Bs[brow * 136 + bc4 * 4]) =
                *(const float4*)(B + (size_t)(k0 + brow) * N + n0 + bc4 * 4);
        }
        __syncthreads();

#pragma unroll
        for (int kk = 0; kk < 16; kk += 8) {
            uint32_t ahi[4][4];
#pragma unroll
            for (int mt = 0; mt < 4; mt++) {
                int mrow = wm0 + mt * 16 + g;
                ahi[mt][0] = f2tf(As[(kk + q) * 136 + mrow]);
                ahi[mt][1] = f2tf(As[(kk + q) * 136 + mrow + 8]);
                ahi[mt][2] = f2tf(As[(kk + q + 4) * 136 + mrow]);
                ahi[mt][3] = f2tf(As[(kk + q + 4) * 136 + mrow + 8]);
            }
            uint32_t bhi[4][2];
#pragma unroll
            for (int nt = 0; nt < 4; nt++) {
                int ncol = wn0 + nt * 8 + g;
                bhi[nt][0] = f2tf(Bs[(kk + q) * 136 + ncol]);
                bhi[nt][1] = f2tf(Bs[(kk + q + 4) * 136 + ncol]);
            }
#pragma unroll
            for (int mt = 0; mt < 4; mt++)
#pragma unroll
                for (int nt = 0; nt < 4; nt++)
                    mma8(acc[mt][nt], ahi[mt][0], ahi[mt][1], ahi[mt][2], ahi[mt][3],
                         bhi[nt][0], bhi[nt][1]);
        }
        __syncthreads();
    }

#pragma unroll
    for (int mt = 0; mt < 4; mt++)
#pragma unroll
        for (int nt = 0; nt < 4; nt++)
#pragma unroll
            for (int e = 0; e < 4; e++) {
                int rowg = m0 + wm0 + mt * 16 + g + ((e >= 2) ? 8 : 0);
                int colg = n0 + wn0 + nt * 8 + 2 * q + (e & 1);
                out[(size_t)rowg * N + colg] = acc[mt][nt][e] + bias[colg];
            }
}

// ===========================================================================
// Flash attention — compensated FP16 (m16n8k16).  grid (SEQ/128, B*H),
// 256 threads (8 warps x 16 q-rows), 64-key blocks, d=96.
//   QK^T: Qhi*Khi + Qlo*Khi + Qhi*Klo   (dropped term ~2^-22, = tf32 scheme)
//   PV:   plain fp16 (11-bit mantissa = tf32-equivalent)
// smem (32-bit words):
//   Khl[key][kp]  : uint2(hi2, lo2), kp=d/2 (0..47), stride 104 words
//   Vp [kpm][d]   : uint2(pack(kp), pack(kp+4)), kpm=ks*4+q', stride 208
//   Pp per warp [cp][g] : uint2(h2(P[g]), h2(P[g+8])), cp=key/2, 16 words/cp
// ===========================================================================
#define KSTW 104                         // words per key row
#define VSTW 208                         // words per kpm row
#define KHL_SZW (64 * KSTW)              // 6656
#define VP_SZW  (16 * VSTW)              // 3328
#define PP_SZW  (8 * 32 * 16)            // 4096
#define ATT_SMEM_WORDS (KHL_SZW + VP_SZW + PP_SZW)   // 14080
#define ATT_SMEM_BYTES (ATT_SMEM_WORDS * 4)          // 56320

__global__ __launch_bounds__(256, 1)
void attn_kernel(const float* __restrict__ gq, const float* __restrict__ gk,
                 const float* __restrict__ gv, const float* __restrict__ gr,
                 float* __restrict__ gatt)
{
    extern __shared__ uint32_t smw[];
    uint32_t* Khl = smw;
    uint32_t* Vp  = smw + KHL_SZW;
    uint32_t* Pp  = smw + KHL_SZW + VP_SZW;

    const int tid  = threadIdx.x;
    const int warp = tid >> 5;
    const int lane = tid & 31;
    const int g = lane >> 2, q = lane & 3;
    const int qr0 = warp * 16;
    uint32_t* Pw = Pp + warp * (32 * 16);

    const int bh = blockIdx.y;
    const int qb = blockIdx.x;
    const size_t base = (size_t)bh * SEQ * HD;

    // ---- Q fragments -> registers, fp16 hi/lo split ONCE ----
    // a0: row g,   d = ks*16+2q,+1 ; a1: row g+8 ; a2/a3: d +8,+9
    const float* qp = gq + base + (size_t)(qb * 128 + qr0) * HD;
    uint32_t qhi[6][4], qlo[6][4];
#pragma unroll
    for (int ks = 0; ks < 6; ks++) {
#pragma unroll
        for (int e = 0; e < 4; e++) {
            int row = (e & 1) ? g + 8 : g;
            int d0  = ks * 16 + 2 * q + ((e >= 2) ? 8 : 0);
            float2 f = *(const float2*)(qp + (size_t)row * HD + d0);
            __half2 h = __floats2half2_rn(f.x, f.y);
            float hx = __half2float(__low2half(h));
            float hy = __half2float(__high2half(h));
            qhi[ks][e] = *reinterpret_cast<uint32_t*>(&h);
            qlo[ks][e] = pack_h2(f.x - hx, f.y - hy);
        }
    }

    float o[12][4];
    float m_a = -1e30f, m_b = -1e30f, l_a = 0.f, l_b = 0.f;
#pragma unroll
    for (int nt = 0; nt < 12; nt++)
#pragma unroll
        for (int e = 0; e < 4; e++) o[nt][e] = 0.f;

    for (int kb = 0; kb < SEQ / 64; kb++) {
        __syncthreads();                       // prev K/V/P fully consumed
        const float* kptr = gk + base + (size_t)kb * 64 * HD;
        const float* vptr = gv + base + (size_t)kb * 64 * HD;

        // K: 64 keys x 24 float4-chunks -> uint4(hi2,lo2,hi2,lo2) per 2 kps
#pragma unroll
        for (int i = 0; i < 6; i++) {
            int u = i * 256 + tid;             // 1536
            int row = u / 24, c4 = u % 24;
            float4 kv = *(const float4*)(kptr + (size_t)row * HD + c4 * 4);
            __half2 h01 = __floats2half2_rn(kv.x, kv.y);
            __half2 h23 = __floats2half2_rn(kv.z, kv.w);
            uint32_t lo01 = pack_h2(kv.x - __half2float(__low2half(h01)),
                                    kv.y - __half2float(__high2half(h01)));
            uint32_t lo23 = pack_h2(kv.z - __half2float(__low2half(h23)),
                                    kv.w - __half2float(__high2half(h23)));
            uint4 w = make_uint4(*reinterpret_cast<uint32_t*>(&h01), lo01,
                                 *reinterpret_cast<uint32_t*>(&h23), lo23);
            *(uint4*)(Khl + row * KSTW + c4 * 4) = w;
        }
        // V: 32 key-pairs x 24 chunks; pack keys (2pk, 2pk+1) per d
#pragma unroll
        for (int i = 0; i < 3; i++) {
            int u = i * 256 + tid;             // 768
            int pk = u / 24, c4 = u % 24;
            const float* va = vptr + (size_t)(2 * pk) * HD + c4 * 4;
            float4 a = *(const float4*)(va);
            float4 b = *(const float4*)(va + HD);
            int j = pk & 7, ks = pk >> 3;
            int kpm  = ks * 4 + (j & 3);
            int slot = (j >= 4) ? 1 : 0;
            uint32_t* vd = Vp + kpm * VSTW + (c4 * 4) * 2 + slot;
            vd[0] = pack_h2(a.x, b.x);
            vd[2] = pack_h2(a.y, b.y);
            vd[4] = pack_h2(a.z, b.z);
            vd[6] = pack_h2(a.w, b.w);
        }
        __syncthreads();

        // ---- S = Q K^T (compensated fp16), 6 ksteps x 8 key-tiles ----
        float s_[8][4];
#pragma unroll
        for (int nt = 0; nt < 8; nt++)
#pragma unroll
            for (int e = 0; e < 4; e++) s_[nt][e] = 0.f;

#pragma unroll
        for (int ks = 0; ks < 6; ks++) {
#pragma unroll
            for (int nt = 0; nt < 8; nt++) {
                const uint32_t* kr = Khl + (nt * 8 + g) * KSTW;
                uint2 w0 = *(const uint2*)(kr + (ks * 8 + q) * 2);       // hi2,lo2
                uint2 w1 = *(const uint2*)(kr + (ks * 8 + q + 4) * 2);
                mma16h(s_[nt], qhi[ks][0], qhi[ks][1], qhi[ks][2], qhi[ks][3],
                       w0.x, w1.x);
                mma16h(s_[nt], qlo[ks][0], qlo[ks][1], qlo[ks][2], qlo[ks][3],
                       w0.x, w1.x);
                mma16h(s_[nt], qhi[ks][0], qhi[ks][1], qhi[ks][2], qhi[ks][3],
                       w0.y, w1.y);
            }
        }

        // ---- online softmax (intra-warp; rows g and g+8) ----
        float mx_a = -1e30f, mx_b = -1e30f;
#pragma unroll
        for (int nt = 0; nt < 8; nt++) {
            mx_a = fmaxf(mx_a, fmaxf(s_[nt][0], s_[nt][1]));
            mx_b = fmaxf(mx_b, fmaxf(s_[nt][2], s_[nt][3]));
        }
        mx_a = fmaxf(mx_a, __shfl_xor_sync(0xffffffffu, mx_a, 1));
        mx_a = fmaxf(mx_a, __shfl_xor_sync(0xffffffffu, mx_a, 2));
        mx_b = fmaxf(mx_b, __shfl_xor_sync(0xffffffffu, mx_b, 1));
        mx_b = fmaxf(mx_b, __shfl_xor_sync(0xffffffffu, mx_b, 2));
        float nm_a = fmaxf(m_a, mx_a), nm_b = fmaxf(m_b, mx_b);
        float sc_a = __expf(m_a - nm_a), sc_b = __expf(m_b - nm_b);
        m_a = nm_a; m_b = nm_b;

        float sum_a = 0.f, sum_b = 0.f;
#pragma unroll
        for (int nt = 0; nt < 8; nt++) {
            float p0 = __expf(s_[nt][0] - nm_a);
            float p1 = __expf(s_[nt][1] - nm_a);
            float p2 = __expf(s_[nt][2] - nm_b);
            float p3 = __expf(s_[nt][3] - nm_b);
            sum_a += p0 + p1; sum_b += p2 + p3;
            int cp = nt * 4 + q;               // cols nt*8+2q, +1
            *(uint2*)(Pw + cp * 16 + g * 2) =
                make_uint2(pack_h2(p0, p1), pack_h2(p2, p3));
        }
        sum_a += __shfl_xor_sync(0xffffffffu, sum_a, 1);
        sum_a += __shfl_xor_sync(0xffffffffu, sum_a, 2);
        sum_b += __shfl_xor_sync(0xffffffffu, sum_b, 1);
        sum_b += __shfl_xor_sync(0xffffffffu, sum_b, 2);
        l_a = l_a * sc_a + sum_a;
        l_b = l_b * sc_b + sum_b;
#pragma unroll
        for (int nt = 0; nt < 12; nt++) {
            o[nt][0] *= sc_a; o[nt][1] *= sc_a;
            o[nt][2] *= sc_b; o[nt][3] *= sc_b;
        }
        __syncwarp();                          // Pw (own warp's rows) visible

        // ---- O += P V (plain fp16), 4 ksteps x 12 d-tiles ----
#pragma unroll
        for (int ks = 0; ks < 4; ks++) {
            uint2 u1 = *(const uint2*)(Pw + (ks * 8 + q) * 16 + g * 2);      // a0,a1
            uint2 u2 = *(const uint2*)(Pw + (ks * 8 + q + 4) * 16 + g * 2);  // a2,a3
#pragma unroll
            for (int nt = 0; nt < 12; nt++) {
                uint2 v2 = *(const uint2*)(Vp + (ks * 4 + q) * VSTW + (nt * 8 + g) * 2);
                mma16h(o[nt], u1.x, u1.y, u2.x, u2.y, v2.x, v2.y);
            }
        }
        __syncwarp();
    }

    // ---- epilogue: /l, *1/sqrt(768), gate r, store (b, n, h*96+d) ----
    const float inv_sqrt_emb = 0.03608439182435161f;
    const int b_ = bh >> 3, h = bh & 7;
    const float li_a = inv_sqrt_emb / l_a;
    const float li_b = inv_sqrt_emb / l_b;
    const int n_a = qb * 128 + qr0 + g;
    const int n_b = n_a + 8;
#pragma unroll
    for (int nt = 0; nt < 12; nt++) {
        int d = nt * 8 + 2 * q;
        float ra0 = gr[base + (size_t)n_a * HD + d];
        float ra1 = gr[base + (size_t)n_a * HD + d + 1];
        float rb0 = gr[base + (size_t)n_b * HD + d];
        float rb1 = gr[base + (size_t)n_b * HD + d + 1];
        size_t oa = ((size_t)(b_ * SEQ + n_a)) * EMB + h * HD + d;
        size_t ob = ((size_t)(b_ * SEQ + n_b)) * EMB + h * HD + d;
        gatt[oa]     = o[nt][0] * li_a * ra0;
        gatt[oa + 1] = o[nt][1] * li_a * ra1;
        gatt[ob]     = o[nt][2] * li_b * rb0;
        gatt[ob + 1] = o[nt][3] * li_b * rb1;
    }
}

// ===========================================================================
extern "C" void kernel_launch(void* const* d_in, const int* in_sizes, int n_in,
                              void* d_out, int out_size)
{
    const float* x      = (const float*)d_in[0];
    const float* w_qkvr = (const float*)d_in[1];
    const float* b_qkvr = (const float*)d_in[2];
    const float* w_proj = (const float*)d_in[3];
    const float* b_proj = (const float*)d_in[4];
    float* out = (float*)d_out;

    cudaFuncSetAttribute(gemm_qkv,
                         cudaFuncAttributeMaxDynamicSharedMemorySize, QKV_SMEM_BYTES);
    cudaFuncSetAttribute(attn_kernel,
                         cudaFuncAttributeMaxDynamicSharedMemorySize, ATT_SMEM_BYTES);

    float *xhl, *whl, *gq, *gk, *gv, *gr, *gatt;
    cudaGetSymbolAddress((void**)&xhl, g_xhl);
    cudaGetSymbolAddress((void**)&whl, g_whl);
    cudaGetSymbolAddress((void**)&gq, g_q);
    cudaGetSymbolAddress((void**)&gk, g_k);
    cudaGetSymbolAddress((void**)&gv, g_v);
    cudaGetSymbolAddress((void**)&gr, g_r);
    cudaGetSymbolAddress((void**)&gatt, g_att);

    split_il<<<MROWS * EMB / 4 / 256, 256>>>(x, xhl, MROWS * EMB / 4);
    split_il<<<EMB * QKVN / 4 / 256, 256>>>(w_qkvr, whl, EMB * QKVN / 4);

    gemm_qkv<<<dim3(QKVN / 128, MROWS / 128), 256, QKV_SMEM_BYTES>>>(
        xhl, whl, b_qkvr);
    attn_kernel<<<dim3(SEQ / 128, BHTOT), 256, ATT_SMEM_BYTES>>>(
        gq, gk, gv, gr, gatt);
    gemm_proj<<<dim3(EMB / 128, MROWS / 128), 256>>>(gatt, w_proj, b_proj, out, EMB);
}

// round 10
// speedup vs baseline: 1.8255x; 1.4056x over previous
#include <cuda_runtime.h>
#include <cuda_fp16.h>
#include <cstdint>

#define EMB   768
#define NHEAD 8
#define HD    96
#define BATCH 2
#define SEQ   4096
#define MROWS (BATCH * SEQ)          // 8192
#define QKVN  (4 * EMB)              // 3072
#define BHTOT (BATCH * NHEAD)        // 16
#define KPTOT (EMB / 2)              // 384 k-pairs

// ---------------- scratch (static device globals; no allocs) ---------------
__device__ uint32_t g_xpk[MROWS * KPTOT * 2];        // x fp16 (hi,lo), [m][kp]
__device__ uint32_t g_wpk[KPTOT * QKVN * 2];         // w fp16 (hi,lo), [kp][n]
__device__ uint32_t g_kpk[BHTOT * SEQ * 96];         // K fp16 (hi,lo), [key][kp]
__device__ uint32_t g_vpk[BHTOT * 64 * 3072];        // V fp16 packed per 64-key block
__device__ float g_q[BHTOT * SEQ * HD];
__device__ float g_k[BHTOT * SEQ * HD];
__device__ float g_v[BHTOT * SEQ * HD];
__device__ float g_r[BHTOT * SEQ * HD];
__device__ float g_att[MROWS * EMB];

// ---------------- helpers ---------------------------------------------------
__device__ __forceinline__ uint32_t f2tf(float x) {
    uint32_t r;
    asm("cvt.rna.tf32.f32 %0, %1;" : "=r"(r) : "f"(x));
    return r;
}

__device__ __forceinline__ void mma8(float* d,
                                     uint32_t a0, uint32_t a1, uint32_t a2, uint32_t a3,
                                     uint32_t b0, uint32_t b1) {
    asm volatile(
        "mma.sync.aligned.m16n8k8.row.col.f32.tf32.tf32.f32 "
        "{%0,%1,%2,%3}, {%4,%5,%6,%7}, {%8,%9}, {%0,%1,%2,%3};"
        : "+f"(d[0]), "+f"(d[1]), "+f"(d[2]), "+f"(d[3])
        : "r"(a0), "r"(a1), "r"(a2), "r"(a3), "r"(b0), "r"(b1));
}

__device__ __forceinline__ void mma16h(float* d,
                                       uint32_t a0, uint32_t a1, uint32_t a2, uint32_t a3,
                                       uint32_t b0, uint32_t b1) {
    asm volatile(
        "mma.sync.aligned.m16n8k16.row.col.f32.f16.f16.f32 "
        "{%0,%1,%2,%3}, {%4,%5,%6,%7}, {%8,%9}, {%0,%1,%2,%3};"
        : "+f"(d[0]), "+f"(d[1]), "+f"(d[2]), "+f"(d[3])
        : "r"(a0), "r"(a1), "r"(a2), "r"(a3), "r"(b0), "r"(b1));
}

__device__ __forceinline__ uint32_t pack_h2(float a, float b) {
    __half2 h = __floats2half2_rn(a, b);
    return *reinterpret_cast<uint32_t*>(&h);
}
// returns hi word; *lo gets residual word (identical math to R9)
__device__ __forceinline__ uint32_t split_h2(float a, float b, uint32_t* lo) {
    __half2 h = __floats2half2_rn(a, b);
    float hx = __half2float(__low2half(h));
    float hy = __half2float(__high2half(h));
    *lo = pack_h2(a - hx, b - hy);
    return *reinterpret_cast<uint32_t*>(&h);
}

__device__ __forceinline__ void cp16w(uint32_t* dst_smem, const uint32_t* src) {
    uint32_t d = (uint32_t)__cvta_generic_to_shared(dst_smem);
    asm volatile("cp.async.cg.shared.global [%0], [%1], 16;\n" :: "r"(d), "l"(src));
}
__device__ __forceinline__ void cp_commit() {
    asm volatile("cp.async.commit_group;\n");
}
template <int N>
__device__ __forceinline__ void cp_wait() {
    asm volatile("cp.async.wait_group %0;\n" :: "n"(N));
}

// ---------------- pack kernels ---------------------------------------------
// x: [m][kp] word pairs; float4 (4 k) -> uint4(hi2,lo2,hi2,lo2)
__global__ void pack_a(const float* __restrict__ in, int n4) {
    int i = blockIdx.x * blockDim.x + threadIdx.x;
    if (i >= n4) return;
    float4 v = ((const float4*)in)[i];
    uint32_t l01, l23;
    uint32_t h01 = split_h2(v.x, v.y, &l01);
    uint32_t h23 = split_h2(v.z, v.w, &l23);
    ((uint4*)g_xpk)[i] = make_uint4(h01, l01, h23, l23);
}
// w: [kp][n] word pairs; reads rows 2kp,2kp+1 cols n..n+3
__global__ void pack_b(const float* __restrict__ in) {
    int u = blockIdx.x * blockDim.x + threadIdx.x;     // kp * (QKVN/4) + n4
    int kp = u / (QKVN / 4), n4 = u % (QKVN / 4);
    const float* p = in + (size_t)(2 * kp) * QKVN + n4 * 4;
    float4 a = *(const float4*)(p);
    float4 b = *(const float4*)(p + QKVN);
    uint32_t lx, ly, lz, lw;
    uint32_t hx = split_h2(a.x, b.x, &lx);
    uint32_t hy = split_h2(a.y, b.y, &ly);
    uint32_t hz = split_h2(a.z, b.z, &lz);
    uint32_t hw = split_h2(a.w, b.w, &lw);
    uint4* o = (uint4*)(g_wpk + ((size_t)kp * QKVN + n4 * 4) * 2);
    o[0] = make_uint4(hx, lx, hy, ly);
    o[1] = make_uint4(hz, lz, hw, lw);
}
// K: per key 48 kp x (hi,lo) = 96 words, same flat index as g_k/24
__global__ void pack_k() {
    int u = blockIdx.x * blockDim.x + threadIdx.x;     // kidx*24 + c4
    int kidx = u / 24, c4 = u % 24;
    float4 v = *(const float4*)(g_k + (size_t)kidx * HD + c4 * 4);
    uint32_t l01, l23;
    uint32_t h01 = split_h2(v.x, v.y, &l01);
    uint32_t h23 = split_h2(v.z, v.w, &l23);
    ((uint4*)g_kpk)[u] = make_uint4(h01, l01, h23, l23);
}
// V: per (bh, kb) block of 3072 words, layout == attn smem Vp (R9 mapping)
__global__ void pack_v() {
    int u = blockIdx.x * blockDim.x + threadIdx.x;     // ((bh*64+kb)*32+pk)*24+c4
    int c4 = u % 24; int t = u / 24;
    int pk = t % 32; int t2 = t / 32;
    int kb = t2 % 64, bh = t2 / 64;
    const float* va = g_v + ((size_t)bh * SEQ + kb * 64 + 2 * pk) * HD + c4 * 4;
    float4 a = *(const float4*)(va);
    float4 b = *(const float4*)(va + HD);
    int j = pk & 7, ks = pk >> 3;
    int kpm  = ks * 4 + (j & 3);
    int slot = (j >= 4) ? 1 : 0;
    uint32_t* vd = g_vpk + ((size_t)(bh * 64 + kb)) * 3072 + kpm * 192 + c4 * 8 + slot;
    vd[0] = pack_h2(a.x, b.x);
    vd[2] = pack_h2(a.y, b.y);
    vd[4] = pack_h2(a.z, b.z);
    vd[6] = pack_h2(a.w, b.w);
}

// ===========================================================================
// QKV GEMM — compensated FP16 (m16n8k16), cp.async 2-stage.
// BM=128 BN=128 BK=16 (8 kp), 256 threads (2x4 warps, 64x32 warp tile).
// sA[m][16 words] stride 16; sB[kp][n*2] stride 272. All frag LDS are .64.
// Epilogue (bias + qkvr scatter) identical to R9.
// ===========================================================================
#define FA_ST 16
#define FB_ST 272
#define FA_SZ (128 * FA_ST)    // 2048
#define FB_SZ (8 * FB_ST)      // 2176
#define QKV_SMEM_BYTES ((2 * FA_SZ + 2 * FB_SZ) * 4)   // 33792

__global__ __launch_bounds__(256, 1)
void gemm_qkv(const float* __restrict__ bias)
{
    extern __shared__ uint32_t smq[];
    uint32_t* sA = smq;                  // [2][FA_SZ]
    uint32_t* sB = smq + 2 * FA_SZ;      // [2][FB_SZ]

    const int N = QKVN;
    const int m0 = blockIdx.y * 128;
    const int n0 = blockIdx.x * 128;
    const int tid  = threadIdx.x;
    const int warp = tid >> 5;
    const int lane = tid & 31;
    const int g = lane >> 2, q = lane & 3;
    const int wm0 = (warp >> 2) * 64;
    const int wn0 = (warp & 3) * 32;

    float acc[4][4][4];
#pragma unroll
    for (int i = 0; i < 4; i++)
#pragma unroll
        for (int j = 0; j < 4; j++)
#pragma unroll
            for (int e = 0; e < 4; e++) acc[i][j][e] = 0.f;

    auto issue = [&](int it8, int s) {          // it8 = tile index (8 kp each)
        uint32_t* Ad = sA + s * FA_SZ;
        uint32_t* Bd = sB + s * FB_SZ;
        int kp0 = it8 * 8;
#pragma
        {
#pragma unroll
            for (int it = 0; it < 2; it++) {
                int u = it * 256 + tid;             // A: 512 chunks
                int arow = u >> 2, ac = (u & 3) * 4;
                cp16w(Ad + arow * FA_ST + ac,
                      g_xpk + ((size_t)(m0 + arow) * KPTOT + kp0) * 2 + ac);
                int brow = u >> 6, bc = (u & 63) * 4;  // B: 512 chunks
                cp16w(Bd + brow * FB_ST + bc,
                      g_wpk + ((size_t)(kp0 + brow) * N + n0) * 2 + bc);
            }
        }
    };

    issue(0, 0);
    cp_commit();

    const int NITER = EMB / 16;                  // 48
    for (int i = 0; i < NITER; i++) {
        int s = i & 1;
        if (i + 1 < NITER) {
            issue(i + 1, s ^ 1);
            cp_commit();
            cp_wait<1>();
        } else {
            cp_wait<0>();
        }
        __syncthreads();

        const uint32_t* Ah = sA + s * FA_SZ;
        const uint32_t* Bh = sB + s * FB_SZ;

        uint32_t ahi[4][4], alo[4][4];
#pragma unroll
        for (int mt = 0; mt < 4; mt++) {
            int mrow = wm0 + mt * 16 + g;
            uint2 x0 = *(const uint2*)(Ah + mrow * FA_ST + q * 2);
            uint2 x1 = *(const uint2*)(Ah + (mrow + 8) * FA_ST + q * 2);
            uint2 x2 = *(const uint2*)(Ah + mrow * FA_ST + q * 2 + 8);
            uint2 x3 = *(const uint2*)(Ah + (mrow + 8) * FA_ST + q * 2 + 8);
            ahi[mt][0] = x0.x; alo[mt][0] = x0.y;
            ahi[mt][1] = x1.x; alo[mt][1] = x1.y;
            ahi[mt][2] = x2.x; alo[mt][2] = x2.y;
            ahi[mt][3] = x3.x; alo[mt][3] = x3.y;
        }
        uint32_t bhi[4][2], blo[4][2];
#pragma unroll
        for (int nt = 0; nt < 4; nt++) {
            int ncol = wn0 + nt * 8 + g;
            uint2 b0 = *(const uint2*)(Bh + q * FB_ST + ncol * 2);
            uint2 b1 = *(const uint2*)(Bh + (q + 4) * FB_ST + ncol * 2);
            bhi[nt][0] = b0.x; blo[nt][0] = b0.y;
            bhi[nt][1] = b1.x; blo[nt][1] = b1.y;
        }
#pragma unroll
        for (int mt = 0; mt < 4; mt++)
#pragma unroll
            for (int nt = 0; nt < 4; nt++) {
                mma16h(acc[mt][nt], ahi[mt][0], ahi[mt][1], ahi[mt][2], ahi[mt][3],
                       bhi[nt][0], bhi[nt][1]);
                mma16h(acc[mt][nt], alo[mt][0], alo[mt][1], alo[mt][2], alo[mt][3],
                       bhi[nt][0], bhi[nt][1]);
                mma16h(acc[mt][nt], ahi[mt][0], ahi[mt][1], ahi[mt][2], ahi[mt][3],
                       blo[nt][0], blo[nt][1]);
            }
        __syncthreads();
    }

    // epilogue — R9 verbatim (bias + raw q/k/v/r scatter)
#pragma unroll
    for (int mt = 0; mt < 4; mt++)
#pragma unroll
        for (int nt = 0; nt < 4; nt++)
#pragma unroll
            for (int e = 0; e < 4; e++) {
                int rowg = m0 + wm0 + mt * 16 + g + ((e >= 2) ? 8 : 0);
                int colg = n0 + wn0 + nt * 8 + 2 * q + (e & 1);
                float val = acc[mt][nt][e] + bias[colg];
                int b_   = rowg >> 12;
                int n    = rowg & 4095;
                int qk   = colg & 3;
                int rest = colg >> 2;
                int d    = rest % 96;
                int h    = rest / 96;
                size_t dst = ((size_t)(b_ * NHEAD + h) * SEQ + n) * HD + d;
                float* t = (qk == 0) ? g_q : (qk == 1) ? g_k : (qk == 2) ? g_v : g_r;
                t[dst] = val;
            }
}

// ===========================================================================
// Out-projection GEMM — R9 verbatim (plain tf32).
// ===========================================================================
__global__ __launch_bounds__(256, 1)
void gemm_proj(const float* __restrict__ A, const float* __restrict__ B,
               const float* __restrict__ bias, float* __restrict__ out, int N)
{
    __shared__ float As[16 * 136];
    __shared__ float Bs[16 * 136];

    const int K  = EMB;
    const int m0 = blockIdx.y * 128;
    const int n0 = blockIdx.x * 128;
    const int tid  = threadIdx.x;
    const int warp = tid >> 5;
    const int lane = tid & 31;
    const int g = lane >> 2, q = lane & 3;
    const int wm0 = (warp >> 2) * 64;
    const int wn0 = (warp & 3) * 32;

    float acc[4][4][4];
#pragma unroll
    for (int i = 0; i < 4; i++)
#pragma unroll
        for (int j = 0; j < 4; j++)
#pragma unroll
            for (int e = 0; e < 4; e++) acc[i][j][e] = 0.f;

    for (int k0 = 0; k0 < K; k0 += 16) {
#pragma unroll
        for (int it = 0; it < 2; it++) {
            int u = it * 256 + tid;
            int arow = u >> 2, ac4 = u & 3;
            float4 av = *(const float4*)(A + (size_t)(m0 + arow) * K + k0 + ac4 * 4);
            As[(ac4 * 4 + 0) * 136 + arow] = av.x;
            As[(ac4 * 4 + 1) * 136 + arow] = av.y;
            As[(ac4 * 4 + 2) * 136 + arow] = av.z;
            As[(ac4 * 4 + 3) * 136 + arow] = av.w;
            int brow = u >> 5, bc4 = u & 31;
            *(float4*)(&Bs[brow * 136 + bc4 * 4]) =
                *(const float4*)(B + (size_t)(k0 + brow) * N + n0 + bc4 * 4);
        }
        __syncthreads();

#pragma unroll
        for (int kk = 0; kk < 16; kk += 8) {
            uint32_t ahi[4][4];
#pragma unroll
            for (int mt = 0; mt < 4; mt++) {
                int mrow = wm0 + mt * 16 + g;
                ahi[mt][0] = f2tf(As[(kk + q) * 136 + mrow]);
                ahi[mt][1] = f2tf(As[(kk + q) * 136 + mrow + 8]);
                ahi[mt][2] = f2tf(As[(kk + q + 4) * 136 + mrow]);
                ahi[mt][3] = f2tf(As[(kk + q + 4) * 136 + mrow + 8]);
            }
            uint32_t bhi[4][2];
#pragma unroll
            for (int nt = 0; nt < 4; nt++) {
                int ncol = wn0 + nt * 8 + g;
                bhi[nt][0] = f2tf(Bs[(kk + q) * 136 + ncol]);
                bhi[nt][1] = f2tf(Bs[(kk + q + 4) * 136 + ncol]);
            }
#pragma unroll
            for (int mt = 0; mt < 4; mt++)
#pragma unroll
                for (int nt = 0; nt < 4; nt++)
                    mma8(acc[mt][nt], ahi[mt][0], ahi[mt][1], ahi[mt][2], ahi[mt][3],
                         bhi[nt][0], bhi[nt][1]);
        }
        __syncthreads();
    }

#pragma unroll
    for (int mt = 0; mt < 4; mt++)
#pragma unroll
        for (int nt = 0; nt < 4; nt++)
#pragma unroll
            for (int e = 0; e < 4; e++) {
                int rowg = m0 + wm0 + mt * 16 + g + ((e >= 2) ? 8 : 0);
                int colg = n0 + wn0 + nt * 8 + 2 * q + (e & 1);
                out[(size_t)rowg * N + colg] = acc[mt][nt][e] + bias[colg];
            }
}

// ===========================================================================
// Flash attention — fp16 compensated, PRE-PACKED K/V + cp.async double buffer.
// Fragment math / smem layouts identical to R9 (Khl stride 104, Vp 208, Pp).
// ===========================================================================
#define KSTW 104
#define VSTW 208
#define KHL_SZW (64 * KSTW)              // 6656 per stage
#define VP_SZW  (16 * VSTW)              // 3328 per stage
#define PP_SZW  (8 * 32 * 16)            // 4096
#define ATT_SMEM_WORDS (2 * KHL_SZW + 2 * VP_SZW + PP_SZW)   // 24064
#define ATT_SMEM_BYTES (ATT_SMEM_WORDS * 4)                  // 96256

__global__ __launch_bounds__(256, 1)
void attn_kernel(const float* __restrict__ gq, const float* __restrict__ gr,
                 float* __restrict__ gatt)
{
    extern __shared__ uint32_t smw[];
    uint32_t* Khl = smw;                         // [2][KHL_SZW]
    uint32_t* Vp  = smw + 2 * KHL_SZW;           // [2][VP_SZW]
    uint32_t* Pp  = smw + 2 * KHL_SZW + 2 * VP_SZW;

    const int tid  = threadIdx.x;
    const int warp = tid >> 5;
    const int lane = tid & 31;
    const int g = lane >> 2, q = lane & 3;
    const int qr0 = warp * 16;
    uint32_t* Pw = Pp + warp * (32 * 16);

    const int bh = blockIdx.y;
    const int qb = blockIdx.x;
    const size_t base = (size_t)bh * SEQ * HD;

    // ---- Q fragments -> registers, fp16 hi/lo split ONCE (R9 verbatim) ----
    const float* qp = gq + base + (size_t)(qb * 128 + qr0) * HD;
    uint32_t qhi[6][4], qlo[6][4];
#pragma unroll
    for (int ks = 0; ks < 6; ks++) {
#pragma unroll
        for (int e = 0; e < 4; e++) {
            int row = (e & 1) ? g + 8 : g;
            int d0  = ks * 16 + 2 * q + ((e >= 2) ? 8 : 0);
            float2 f = *(const float2*)(qp + (size_t)row * HD + d0);
            qhi[ks][e] = split_h2(f.x, f.y, &qlo[ks][e]);
        }
    }

    auto issue = [&](int kb, int s) {
        const uint32_t* ksrc = g_kpk + ((size_t)bh * SEQ + kb * 64) * 96;
        const uint32_t* vsrc = g_vpk + ((size_t)(bh * 64 + kb)) * 3072;
        uint32_t* Kd = Khl + s * KHL_SZW;
        uint32_t* Vd = Vp + s * VP_SZW;
#pragma unroll
        for (int i = 0; i < 6; i++) {            // K: 1536 chunks
            int u = i * 256 + tid;
            int row = u / 24, c4 = u % 24;
            cp16w(Kd + row * KSTW + c4 * 4, ksrc + row * 96 + c4 * 4);
        }
#pragma unroll
        for (int i = 0; i < 3; i++) {            // V: 768 chunks
            int u = i * 256 + tid;
            int r = u / 48, c = u % 48;
            cp16w(Vd + r * VSTW + c * 4, vsrc + r * 192 + c * 4);
        }
    };

    float o[12][4];
    float m_a = -1e30f, m_b = -1e30f, l_a = 0.f, l_b = 0.f;
#pragma unroll
    for (int nt = 0; nt < 12; nt++)
#pragma unroll
        for (int e = 0; e < 4; e++) o[nt][e] = 0.f;

    issue(0, 0);
    cp_commit();

    const int NKB = SEQ / 64;                    // 64
    for (int kb = 0; kb < NKB; kb++) {
        int s = kb & 1;
        if (kb + 1 < NKB) {
            issue(kb + 1, s ^ 1);
            cp_commit();
            cp_wait<1>();
        } else {
            cp_wait<0>();
        }
        __syncthreads();

        const uint32_t* Kh = Khl + s * KHL_SZW;
        const uint32_t* Vh = Vp + s * VP_SZW;

        // ---- S = Q K^T (compensated fp16) — R9 verbatim ----
        float s_[8][4];
#pragma unroll
        for (int nt = 0; nt < 8; nt++)
#pragma unroll
            for (int e = 0; e < 4; e++) s_[nt][e] = 0.f;

#pragma unroll
        for (int ks = 0; ks < 6; ks++) {
#pragma unroll
            for (int nt = 0; nt < 8; nt++) {
                const uint32_t* kr = Kh + (nt * 8 + g) * KSTW;
                uint2 w0 = *(const uint2*)(kr + (ks * 8 + q) * 2);
                uint2 w1 = *(const uint2*)(kr + (ks * 8 + q + 4) * 2);
                mma16h(s_[nt], qhi[ks][0], qhi[ks][1], qhi[ks][2], qhi[ks][3],
                       w0.x, w1.x);
                mma16h(s_[nt], qlo[ks][0], qlo[ks][1], qlo[ks][2], qlo[ks][3],
                       w0.x, w1.x);
                mma16h(s_[nt], qhi[ks][0], qhi[ks][1], qhi[ks][2], qhi[ks][3],
                       w0.y, w1.y);
            }
        }

        // ---- online softmax (intra-warp) — R9 verbatim ----
        float mx_a = -1e30f, mx_b = -1e30f;
#pragma unroll
        for (int nt = 0; nt < 8; nt++) {
            mx_a = fmaxf(mx_a, fmaxf(s_[nt][0], s_[nt][1]));
            mx_b = fmaxf(mx_b, fmaxf(s_[nt][2], s_[nt][3]));
        }
        mx_a = fmaxf(mx_a, __shfl_xor_sync(0xffffffffu, mx_a, 1));
        mx_a = fmaxf(mx_a, __shfl_xor_sync(0xffffffffu, mx_a, 2));
        mx_b = fmaxf(mx_b, __shfl_xor_sync(0xffffffffu, mx_b, 1));
        mx_b = fmaxf(mx_b, __shfl_xor_sync(0xffffffffu, mx_b, 2));
        float nm_a = fmaxf(m_a, mx_a), nm_b = fmaxf(m_b, mx_b);
        float sc_a = __expf(m_a - nm_a), sc_b = __expf(m_b - nm_b);
        m_a = nm_a; m_b = nm_b;

        float sum_a = 0.f, sum_b = 0.f;
#pragma unroll
        for (int nt = 0; nt < 8; nt++) {
            float p0 = __expf(s_[nt][0] - nm_a);
            float p1 = __expf(s_[nt][1] - nm_a);
            float p2 = __expf(s_[nt][2] - nm_b);
            float p3 = __expf(s_[nt][3] - nm_b);
            sum_a += p0 + p1; sum_b += p2 + p3;
            int cp = nt * 4 + q;
            *(uint2*)(Pw + cp * 16 + g * 2) =
                make_uint2(pack_h2(p0, p1), pack_h2(p2, p3));
        }
        sum_a += __shfl_xor_sync(0xffffffffu, sum_a, 1);
        sum_a += __shfl_xor_sync(0xffffffffu, sum_a, 2);
        sum_b += __shfl_xor_sync(0xffffffffu, sum_b, 1);
        sum_b += __shfl_xor_sync(0xffffffffu, sum_b, 2);
        l_a = l_a * sc_a + sum_a;
        l_b = l_b * sc_b + sum_b;
#pragma unroll
        for (int nt = 0; nt < 12; nt++) {
            o[nt][0] *= sc_a; o[nt][1] *= sc_a;
            o[nt][2] *= sc_b; o[nt][3] *= sc_b;
        }
        __syncwarp();

        // ---- O += P V (plain fp16) — R9 verbatim ----
#pragma unroll
        for (int ks = 0; ks < 4; ks++) {
            uint2 u1 = *(const uint2*)(Pw + (ks * 8 + q) * 16 + g * 2);
            uint2 u2 = *(const uint2*)(Pw + (ks * 8 + q + 4) * 16 + g * 2);
#pragma unroll
            for (int nt = 0; nt < 12; nt++) {
                uint2 v2 = *(const uint2*)(Vh + (ks * 4 + q) * VSTW + (nt * 8 + g) * 2);
                mma16h(o[nt], u1.x, u1.y, u2.x, u2.y, v2.x, v2.y);
            }
        }
        __syncthreads();                         // stage s fully consumed
    }

    // ---- epilogue — R9 verbatim ----
    const float inv_sqrt_emb = 0.03608439182435161f;
    const int b_ = bh >> 3, h = bh & 7;
    const float li_a = inv_sqrt_emb / l_a;
    const float li_b = inv_sqrt_emb / l_b;
    const int n_a = qb * 128 + qr0 + g;
    const int n_b = n_a + 8;
#pragma unroll
    for (int nt = 0; nt < 12; nt++) {
        int d = nt * 8 + 2 * q;
        float ra0 = gr[base + (size_t)n_a * HD + d];
        float ra1 = gr[base + (size_t)n_a * HD + d + 1];
        float rb0 = gr[base + (size_t)n_b * HD + d];
        float rb1 = gr[base + (size_t)n_b * HD + d + 1];
        size_t oa = ((size_t)(b_ * SEQ + n_a)) * EMB + h * HD + d;
        size_t ob = ((size_t)(b_ * SEQ + n_b)) * EMB + h * HD + d;
        gatt[oa]     = o[nt][0] * li_a * ra0;
        gatt[oa + 1] = o[nt][1] * li_a * ra1;
        gatt[ob]     = o[nt][2] * li_b * rb0;
        gatt[ob + 1] = o[nt][3] * li_b * rb1;
    }
}

// ===========================================================================
extern "C" void kernel_launch(void* const* d_in, const int* in_sizes, int n_in,
                              void* d_out, int out_size)
{
    const float* x      = (const float*)d_in[0];
    const float* w_qkvr = (const float*)d_in[1];
    const float* b_qkvr = (const float*)d_in[2];
    const float* w_proj = (const float*)d_in[3];
    const float* b_proj = (const float*)d_in[4];
    float* out = (float*)d_out;

    cudaFuncSetAttribute(gemm_qkv,
                         cudaFuncAttributeMaxDynamicSharedMemorySize, QKV_SMEM_BYTES);
    cudaFuncSetAttribute(attn_kernel,
                         cudaFuncAttributeMaxDynamicSharedMemorySize, ATT_SMEM_BYTES);

    float *gq, *gr, *gatt;
    cudaGetSymbolAddress((void**)&gq, g_q);
    cudaGetSymbolAddress((void**)&gr, g_r);
    cudaGetSymbolAddress((void**)&gatt, g_att);

    pack_a<<<MROWS * EMB / 4 / 256, 256>>>(x, MROWS * EMB / 4);
    pack_b<<<KPTOT * (QKVN / 4) / 256, 256>>>(w_qkvr);

    gemm_qkv<<<dim3(QKVN / 128, MROWS / 128), 256, QKV_SMEM_BYTES>>>(b_qkvr);

    pack_k<<<BHTOT * SEQ * 24 / 256, 256>>>();
    pack_v<<<BHTOT * 64 * 32 * 24 / 256, 256>>>();

    attn_kernel<<<dim3(SEQ / 128, BHTOT), 256, ATT_SMEM_BYTES>>>(gq, gr, gatt);
    gemm_proj<<<dim3(EMB / 128, MROWS / 128), 256>>>(gatt, w_proj, b_proj, out, EMB);
}

// round 11
// speedup vs baseline: 2.0259x; 1.1098x over previous
#include <cuda_runtime.h>
#include <cuda_fp16.h>
#include <cstdint>

#define EMB   768
#define NHEAD 8
#define HD    96
#define BATCH 2
#define SEQ   4096
#define MROWS (BATCH * SEQ)          // 8192
#define QKVN  (4 * EMB)              // 3072
#define BHTOT (BATCH * NHEAD)        // 16
#define KPTOT (EMB / 2)              // 384 k-pairs

// ---------------- scratch (static device globals; no allocs) ---------------
__device__ uint32_t g_xpk[MROWS * KPTOT * 2];        // x fp16 (hi,lo), [m][kp]
__device__ uint32_t g_wpk[KPTOT * QKVN * 2];         // w fp16 (hi,lo), [kp][n]
__device__ uint32_t g_kpk[BHTOT * SEQ * 96];         // K fp16 (hi,lo), [key][kp]
__device__ uint32_t g_vpk[BHTOT * 64 * 3072];        // V fp16 packed per 64-key block
__device__ float g_q[BHTOT * SEQ * HD];
__device__ float g_k[BHTOT * SEQ * HD];
__device__ float g_v[BHTOT * SEQ * HD];
__device__ float g_r[BHTOT * SEQ * HD];
__device__ float g_att[MROWS * EMB];

// ---------------- helpers ---------------------------------------------------
__device__ __forceinline__ uint32_t f2tf(float x) {
    uint32_t r;
    asm("cvt.rna.tf32.f32 %0, %1;" : "=r"(r) : "f"(x));
    return r;
}

__device__ __forceinline__ void mma8(float* d,
                                     uint32_t a0, uint32_t a1, uint32_t a2, uint32_t a3,
                                     uint32_t b0, uint32_t b1) {
    asm volatile(
        "mma.sync.aligned.m16n8k8.row.col.f32.tf32.tf32.f32 "
        "{%0,%1,%2,%3}, {%4,%5,%6,%7}, {%8,%9}, {%0,%1,%2,%3};"
        : "+f"(d[0]), "+f"(d[1]), "+f"(d[2]), "+f"(d[3])
        : "r"(a0), "r"(a1), "r"(a2), "r"(a3), "r"(b0), "r"(b1));
}

__device__ __forceinline__ void mma16h(float* d,
                                       uint32_t a0, uint32_t a1, uint32_t a2, uint32_t a3,
                                       uint32_t b0, uint32_t b1) {
    asm volatile(
        "mma.sync.aligned.m16n8k16.row.col.f32.f16.f16.f32 "
        "{%0,%1,%2,%3}, {%4,%5,%6,%7}, {%8,%9}, {%0,%1,%2,%3};"
        : "+f"(d[0]), "+f"(d[1]), "+f"(d[2]), "+f"(d[3])
        : "r"(a0), "r"(a1), "r"(a2), "r"(a3), "r"(b0), "r"(b1));
}

__device__ __forceinline__ uint32_t pack_h2(float a, float b) {
    __half2 h = __floats2half2_rn(a, b);
    return *reinterpret_cast<uint32_t*>(&h);
}
__device__ __forceinline__ uint32_t split_h2(float a, float b, uint32_t* lo) {
    __half2 h = __floats2half2_rn(a, b);
    float hx = __half2float(__low2half(h));
    float hy = __half2float(__high2half(h));
    *lo = pack_h2(a - hx, b - hy);
    return *reinterpret_cast<uint32_t*>(&h);
}

__device__ __forceinline__ void cp16w(uint32_t* dst_smem, const uint32_t* src) {
    uint32_t d = (uint32_t)__cvta_generic_to_shared(dst_smem);
    asm volatile("cp.async.cg.shared.global [%0], [%1], 16;\n" :: "r"(d), "l"(src));
}
__device__ __forceinline__ void cp_commit() {
    asm volatile("cp.async.commit_group;\n");
}
template <int N>
__device__ __forceinline__ void cp_wait() {
    asm volatile("cp.async.wait_group %0;\n" :: "n"(N));
}

// ---------------- pack kernels — R10 verbatim -------------------------------
__global__ void pack_a(const float* __restrict__ in, int n4) {
    int i = blockIdx.x * blockDim.x + threadIdx.x;
    if (i >= n4) return;
    float4 v = ((const float4*)in)[i];
    uint32_t l01, l23;
    uint32_t h01 = split_h2(v.x, v.y, &l01);
    uint32_t h23 = split_h2(v.z, v.w, &l23);
    ((uint4*)g_xpk)[i] = make_uint4(h01, l01, h23, l23);
}
__global__ void pack_b(const float* __restrict__ in) {
    int u = blockIdx.x * blockDim.x + threadIdx.x;
    int kp = u / (QKVN / 4), n4 = u % (QKVN / 4);
    const float* p = in + (size_t)(2 * kp) * QKVN + n4 * 4;
    float4 a = *(const float4*)(p);
    float4 b = *(const float4*)(p + QKVN);
    uint32_t lx, ly, lz, lw;
    uint32_t hx = split_h2(a.x, b.x, &lx);
    uint32_t hy = split_h2(a.y, b.y, &ly);
    uint32_t hz = split_h2(a.z, b.z, &lz);
    uint32_t hw = split_h2(a.w, b.w, &lw);
    uint4* o = (uint4*)(g_wpk + ((size_t)kp * QKVN + n4 * 4) * 2);
    o[0] = make_uint4(hx, lx, hy, ly);
    o[1] = make_uint4(hz, lz, hw, lw);
}
__global__ void pack_k() {
    int u = blockIdx.x * blockDim.x + threadIdx.x;
    int kidx = u / 24, c4 = u % 24;
    float4 v = *(const float4*)(g_k + (size_t)kidx * HD + c4 * 4);
    uint32_t l01, l23;
    uint32_t h01 = split_h2(v.x, v.y, &l01);
    uint32_t h23 = split_h2(v.z, v.w, &l23);
    ((uint4*)g_kpk)[u] = make_uint4(h01, l01, h23, l23);
}
__global__ void pack_v() {
    int u = blockIdx.x * blockDim.x + threadIdx.x;
    int c4 = u % 24; int t = u / 24;
    int pk = t % 32; int t2 = t / 32;
    int kb = t2 % 64, bh = t2 / 64;
    const float* va = g_v + ((size_t)bh * SEQ + kb * 64 + 2 * pk) * HD + c4 * 4;
    float4 a = *(const float4*)(va);
    float4 b = *(const float4*)(va + HD);
    int j = pk & 7, ks = pk >> 3;
    int kpm  = ks * 4 + (j & 3);
    int slot = (j >= 4) ? 1 : 0;
    uint32_t* vd = g_vpk + ((size_t)(bh * 64 + kb)) * 3072 + kpm * 192 + c4 * 8 + slot;
    vd[0] = pack_h2(a.x, b.x);
    vd[2] = pack_h2(a.y, b.y);
    vd[4] = pack_h2(a.z, b.z);
    vd[6] = pack_h2(a.w, b.w);
}

// ===========================================================================
// QKV GEMM — R10 verbatim (compensated FP16, cp.async 2-stage).
// ===========================================================================
#define FA_ST 16
#define FB_ST 272
#define FA_SZ (128 * FA_ST)    // 2048
#define FB_SZ (8 * FB_ST)      // 2176
#define QKV_SMEM_BYTES ((2 * FA_SZ + 2 * FB_SZ) * 4)   // 33792

__global__ __launch_bounds__(256, 1)
void gemm_qkv(const float* __restrict__ bias)
{
    extern __shared__ uint32_t smq[];
    uint32_t* sA = smq;
    uint32_t* sB = smq + 2 * FA_SZ;

    const int N = QKVN;
    const int m0 = blockIdx.y * 128;
    const int n0 = blockIdx.x * 128;
    const int tid  = threadIdx.x;
    const int warp = tid >> 5;
    const int lane = tid & 31;
    const int g = lane >> 2, q = lane & 3;
    const int wm0 = (warp >> 2) * 64;
    const int wn0 = (warp & 3) * 32;

    float acc[4][4][4];
#pragma unroll
    for (int i = 0; i < 4; i++)
#pragma unroll
        for (int j = 0; j < 4; j++)
#pragma unroll
            for (int e = 0; e < 4; e++) acc[i][j][e] = 0.f;

    auto issue = [&](int it8, int s) {
        uint32_t* Ad = sA + s * FA_SZ;
        uint32_t* Bd = sB + s * FB_SZ;
        int kp0 = it8 * 8;
#pragma unroll
        for (int it = 0; it < 2; it++) {
            int u = it * 256 + tid;
            int arow = u >> 2, ac = (u & 3) * 4;
            cp16w(Ad + arow * FA_ST + ac,
                  g_xpk + ((size_t)(m0 + arow) * KPTOT + kp0) * 2 + ac);
            int brow = u >> 6, bc = (u & 63) * 4;
            cp16w(Bd + brow * FB_ST + bc,
                  g_wpk + ((size_t)(kp0 + brow) * N + n0) * 2 + bc);
        }
    };

    issue(0, 0);
    cp_commit();

    const int NITER = EMB / 16;
    for (int i = 0; i < NITER; i++) {
        int s = i & 1;
        if (i + 1 < NITER) {
            issue(i + 1, s ^ 1);
            cp_commit();
            cp_wait<1>();
        } else {
            cp_wait<0>();
        }
        __syncthreads();

        const uint32_t* Ah = sA + s * FA_SZ;
        const uint32_t* Bh = sB + s * FB_SZ;

        uint32_t ahi[4][4], alo[4][4];
#pragma unroll
        for (int mt = 0; mt < 4; mt++) {
            int mrow = wm0 + mt * 16 + g;
            uint2 x0 = *(const uint2*)(Ah + mrow * FA_ST + q * 2);
            uint2 x1 = *(const uint2*)(Ah + (mrow + 8) * FA_ST + q * 2);
            uint2 x2 = *(const uint2*)(Ah + mrow * FA_ST + q * 2 + 8);
            uint2 x3 = *(const uint2*)(Ah + (mrow + 8) * FA_ST + q * 2 + 8);
            ahi[mt][0] = x0.x; alo[mt][0] = x0.y;
            ahi[mt][1] = x1.x; alo[mt][1] = x1.y;
            ahi[mt][2] = x2.x; alo[mt][2] = x2.y;
            ahi[mt][3] = x3.x; alo[mt][3] = x3.y;
        }
        uint32_t bhi[4][2], blo[4][2];
#pragma unroll
        for (int nt = 0; nt < 4; nt++) {
            int ncol = wn0 + nt * 8 + g;
            uint2 b0 = *(const uint2*)(Bh + q * FB_ST + ncol * 2);
            uint2 b1 = *(const uint2*)(Bh + (q + 4) * FB_ST + ncol * 2);
            bhi[nt][0] = b0.x; blo[nt][0] = b0.y;
            bhi[nt][1] = b1.x; blo[nt][1] = b1.y;
        }
#pragma unroll
        for (int mt = 0; mt < 4; mt++)
#pragma unroll
            for (int nt = 0; nt < 4; nt++) {
                mma16h(acc[mt][nt], ahi[mt][0], ahi[mt][1], ahi[mt][2], ahi[mt][3],
                       bhi[nt][0], bhi[nt][1]);
                mma16h(acc[mt][nt], alo[mt][0], alo[mt][1], alo[mt][2], alo[mt][3],
                       bhi[nt][0], bhi[nt][1]);
                mma16h(acc[mt][nt], ahi[mt][0], ahi[mt][1], ahi[mt][2], ahi[mt][3],
                       blo[nt][0], blo[nt][1]);
            }
        __syncthreads();
    }

#pragma unroll
    for (int mt = 0; mt < 4; mt++)
#pragma unroll
        for (int nt = 0; nt < 4; nt++)
#pragma unroll
            for (int e = 0; e < 4; e++) {
                int rowg = m0 + wm0 + mt * 16 + g + ((e >= 2) ? 8 : 0);
                int colg = n0 + wn0 + nt * 8 + 2 * q + (e & 1);
                float val = acc[mt][nt][e] + bias[colg];
                int b_   = rowg >> 12;
                int n    = rowg & 4095;
                int qk   = colg & 3;
                int rest = colg >> 2;
                int d    = rest % 96;
                int h    = rest / 96;
                size_t dst = ((size_t)(b_ * NHEAD + h) * SEQ + n) * HD + d;
                float* t = (qk == 0) ? g_q : (qk == 1) ? g_k : (qk == 2) ? g_v : g_r;
                t[dst] = val;
            }
}

// ===========================================================================
// Out-projection GEMM — R10 verbatim (plain tf32).
// ===========================================================================
__global__ __launch_bounds__(256, 1)
void gemm_proj(const float* __restrict__ A, const float* __restrict__ B,
               const float* __restrict__ bias, float* __restrict__ out, int N)
{
    __shared__ float As[16 * 136];
    __shared__ float Bs[16 * 136];

    const int K  = EMB;
    const int m0 = blockIdx.y * 128;
    const int n0 = blockIdx.x * 128;
    const int tid  = threadIdx.x;
    const int warp = tid >> 5;
    const int lane = tid & 31;
    const int g = lane >> 2, q = lane & 3;
    const int wm0 = (warp >> 2) * 64;
    const int wn0 = (warp & 3) * 32;

    float acc[4][4][4];
#pragma unroll
    for (int i = 0; i < 4; i++)
#pragma unroll
        for (int j = 0; j < 4; j++)
#pragma unroll
            for (int e = 0; e < 4; e++) acc[i][j][e] = 0.f;

    for (int k0 = 0; k0 < K; k0 += 16) {
#pragma unroll
        for (int it = 0; it < 2; it++) {
            int u = it * 256 + tid;
            int arow = u >> 2, ac4 = u & 3;
            float4 av = *(const float4*)(A + (size_t)(m0 + arow) * K + k0 + ac4 * 4);
            As[(ac4 * 4 + 0) * 136 + arow] = av.x;
            As[(ac4 * 4 + 1) * 136 + arow] = av.y;
            As[(ac4 * 4 + 2) * 136 + arow] = av.z;
            As[(ac4 * 4 + 3) * 136 + arow] = av.w;
            int brow = u >> 5, bc4 = u & 31;
            *(float4*)(&Bs[brow * 136 + bc4 * 4]) =
                *(const float4*)(B + (size_t)(k0 + brow) * N + n0 + bc4 * 4);
        }
        __syncthreads();

#pragma unroll
        for (int kk = 0; kk < 16; kk += 8) {
            uint32_t ahi[4][4];
#pragma unroll
            for (int mt = 0; mt < 4; mt++) {
                int mrow = wm0 + mt * 16 + g;
                ahi[mt][0] = f2tf(As[(kk + q) * 136 + mrow]);
                ahi[mt][1] = f2tf(As[(kk + q) * 136 + mrow + 8]);
                ahi[mt][2] = f2tf(As[(kk + q + 4) * 136 + mrow]);
                ahi[mt][3] = f2tf(As[(kk + q + 4) * 136 + mrow + 8]);
            }
            uint32_t bhi[4][2];
#pragma unroll
            for (int nt = 0; nt < 4; nt++) {
                int ncol = wn0 + nt * 8 + g;
                bhi[nt][0] = f2tf(Bs[(kk + q) * 136 + ncol]);
                bhi[nt][1] = f2tf(Bs[(kk + q + 4) * 136 + ncol]);
            }
#pragma unroll
            for (int mt = 0; mt < 4; mt++)
#pragma unroll
                for (int nt = 0; nt < 4; nt++)
                    mma8(acc[mt][nt], ahi[mt][0], ahi[mt][1], ahi[mt][2], ahi[mt][3],
                         bhi[nt][0], bhi[nt][1]);
        }
        __syncthreads();
    }

#pragma unroll
    for (int mt = 0; mt < 4; mt++)
#pragma unroll
        for (int nt = 0; nt < 4; nt++)
#pragma unroll
            for (int e = 0; e < 4; e++) {
                int rowg = m0 + wm0 + mt * 16 + g + ((e >= 2) ? 8 : 0);
                int colg = n0 + wn0 + nt * 8 + 2 * q + (e & 1);
                out[(size_t)rowg * N + colg] = acc[mt][nt][e] + bias[colg];
            }
}

// ===========================================================================
// Flash attention — R10 math verbatim, restructured to 128-thread CTAs
// (4 warps, 64 q-rows) so TWO CTAs co-reside per SM (smem 88KB, regs OK).
// Per-warp fragments, smem layouts, and numerics are bit-identical to R10.
// ===========================================================================
#define KSTW 104
#define VSTW 208
#define KHL_SZW (64 * KSTW)              // 6656 per stage
#define VP_SZW  (16 * VSTW)              // 3328 per stage
#define PP_SZW  (4 * 32 * 16)            // 2048 (4 warps)
#define ATT_SMEM_WORDS (2 * KHL_SZW + 2 * VP_SZW + PP_SZW)   // 22016
#define ATT_SMEM_BYTES (ATT_SMEM_WORDS * 4)                  // 88064

__global__ __launch_bounds__(128, 2)
void attn_kernel(const float* __restrict__ gq, const float* __restrict__ gr,
                 float* __restrict__ gatt)
{
    extern __shared__ uint32_t smw[];
    uint32_t* Khl = smw;                         // [2][KHL_SZW]
    uint32_t* Vp  = smw + 2 * KHL_SZW;           // [2][VP_SZW]
    uint32_t* Pp  = smw + 2 * KHL_SZW + 2 * VP_SZW;

    const int tid  = threadIdx.x;
    const int warp = tid >> 5;                   // 0..3
    const int lane = tid & 31;
    const int g = lane >> 2, q = lane & 3;
    const int qr0 = warp * 16;                   // 0..48
    uint32_t* Pw = Pp + warp * (32 * 16);

    const int bh = blockIdx.y;
    const int qb = blockIdx.x;                   // 64 q-blocks of 64 rows
    const size_t base = (size_t)bh * SEQ * HD;

    // ---- Q fragments -> registers, fp16 hi/lo split ONCE ----
    const float* qp = gq + base + (size_t)(qb * 64 + qr0) * HD;
    uint32_t qhi[6][4], qlo[6][4];
#pragma unroll
    for (int ks = 0; ks < 6; ks++) {
#pragma unroll
        for (int e = 0; e < 4; e++) {
            int row = (e & 1) ? g + 8 : g;
            int d0  = ks * 16 + 2 * q + ((e >= 2) ? 8 : 0);
            float2 f = *(const float2*)(qp + (size_t)row * HD + d0);
            qhi[ks][e] = split_h2(f.x, f.y, &qlo[ks][e]);
        }
    }

    auto issue = [&](int kb, int s) {
        const uint32_t* ksrc = g_kpk + ((size_t)bh * SEQ + kb * 64) * 96;
        const uint32_t* vsrc = g_vpk + ((size_t)(bh * 64 + kb)) * 3072;
        uint32_t* Kd = Khl + s * KHL_SZW;
        uint32_t* Vd = Vp + s * VP_SZW;
#pragma unroll
        for (int i = 0; i < 12; i++) {           // K: 1536 chunks / 128 thr
            int u = i * 128 + tid;
            int row = u / 24, c4 = u % 24;
            cp16w(Kd + row * KSTW + c4 * 4, ksrc + row * 96 + c4 * 4);
        }
#pragma unroll
        for (int i = 0; i < 6; i++) {            // V: 768 chunks / 128 thr
            int u = i * 128 + tid;
            int r = u / 48, c = u % 48;
            cp16w(Vd + r * VSTW + c * 4, vsrc + r * 192 + c * 4);
        }
    };

    float o[12][4];
    float m_a = -1e30f, m_b = -1e30f, l_a = 0.f, l_b = 0.f;
#pragma unroll
    for (int nt = 0; nt < 12; nt++)
#pragma unroll
        for (int e = 0; e < 4; e++) o[nt][e] = 0.f;

    issue(0, 0);
    cp_commit();

    const int NKB = SEQ / 64;                    // 64
    for (int kb = 0; kb < NKB; kb++) {
        int s = kb & 1;
        if (kb + 1 < NKB) {
            issue(kb + 1, s ^ 1);
            cp_commit();
            cp_wait<1>();
        } else {
            cp_wait<0>();
        }
        __syncthreads();

        const uint32_t* Kh = Khl + s * KHL_SZW;
        const uint32_t* Vh = Vp + s * VP_SZW;

        // ---- S = Q K^T (compensated fp16) ----
        float s_[8][4];
#pragma unroll
        for (int nt = 0; nt < 8; nt++)
#pragma unroll
            for (int e = 0; e < 4; e++) s_[nt][e] = 0.f;

#pragma unroll
        for (int ks = 0; ks < 6; ks++) {
#pragma unroll
            for (int nt = 0; nt < 8; nt++) {
                const uint32_t* kr = Kh + (nt * 8 + g) * KSTW;
                uint2 w0 = *(const uint2*)(kr + (ks * 8 + q) * 2);
                uint2 w1 = *(const uint2*)(kr + (ks * 8 + q + 4) * 2);
                mma16h(s_[nt], qhi[ks][0], qhi[ks][1], qhi[ks][2], qhi[ks][3],
                       w0.x, w1.x);
                mma16h(s_[nt], qlo[ks][0], qlo[ks][1], qlo[ks][2], qlo[ks][3],
                       w0.x, w1.x);
                mma16h(s_[nt], qhi[ks][0], qhi[ks][1], qhi[ks][2], qhi[ks][3],
                       w0.y, w1.y);
            }
        }

        // ---- online softmax (intra-warp; rows g and g+8) ----
        float mx_a = -1e30f, mx_b = -1e30f;
#pragma unroll
        for (int nt = 0; nt < 8; nt++) {
            mx_a = fmaxf(mx_a, fmaxf(s_[nt][0], s_[nt][1]));
            mx_b = fmaxf(mx_b, fmaxf(s_[nt][2], s_[nt][3]));
        }
        mx_a = fmaxf(mx_a, __shfl_xor_sync(0xffffffffu, mx_a, 1));
        mx_a = fmaxf(mx_a, __shfl_xor_sync(0xffffffffu, mx_a, 2));
        mx_b = fmaxf(mx_b, __shfl_xor_sync(0xffffffffu, mx_b, 1));
        mx_b = fmaxf(mx_b, __shfl_xor_sync(0xffffffffu, mx_b, 2));
        float nm_a = fmaxf(m_a, mx_a), nm_b = fmaxf(m_b, mx_b);
        float sc_a = __expf(m_a - nm_a), sc_b = __expf(m_b - nm_b);
        m_a = nm_a; m_b = nm_b;

        float sum_a = 0.f, sum_b = 0.f;
#pragma unroll
        for (int nt = 0; nt < 8; nt++) {
            float p0 = __expf(s_[nt][0] - nm_a);
            float p1 = __expf(s_[nt][1] - nm_a);
            float p2 = __expf(s_[nt][2] - nm_b);
            float p3 = __expf(s_[nt][3] - nm_b);
            sum_a += p0 + p1; sum_b += p2 + p3;
            int cp = nt * 4 + q;
            *(uint2*)(Pw + cp * 16 + g * 2) =
                make_uint2(pack_h2(p0, p1), pack_h2(p2, p3));
        }
        sum_a += __shfl_xor_sync(0xffffffffu, sum_a, 1);
        sum_a += __shfl_xor_sync(0xffffffffu, sum_a, 2);
        sum_b += __shfl_xor_sync(0xffffffffu, sum_b, 1);
        sum_b += __shfl_xor_sync(0xffffffffu, sum_b, 2);
        l_a = l_a * sc_a + sum_a;
        l_b = l_b * sc_b + sum_b;
#pragma unroll
        for (int nt = 0; nt < 12; nt++) {
            o[nt][0] *= sc_a; o[nt][1] *= sc_a;
            o[nt][2] *= sc_b; o[nt][3] *= sc_b;
        }
        __syncwarp();

        // ---- O += P V (plain fp16) ----
#pragma unroll
        for (int ks = 0; ks < 4; ks++) {
            uint2 u1 = *(const uint2*)(Pw + (ks * 8 + q) * 16 + g * 2);
            uint2 u2 = *(const uint2*)(Pw + (ks * 8 + q + 4) * 16 + g * 2);
#pragma unroll
            for (int nt = 0; nt < 12; nt++) {
                uint2 v2 = *(const uint2*)(Vh + (ks * 4 + q) * VSTW + (nt * 8 + g) * 2);
                mma16h(o[nt], u1.x, u1.y, u2.x, u2.y, v2.x, v2.y);
            }
        }
        __syncthreads();                         // stage s fully consumed
    }

    // ---- epilogue — R10 math, 64-row q-block ----
    const float inv_sqrt_emb = 0.03608439182435161f;
    const int b_ = bh >> 3, h = bh & 7;
    const float li_a = inv_sqrt_emb / l_a;
    const float li_b = inv_sqrt_emb / l_b;
    const int n_a = qb * 64 + qr0 + g;
    const int n_b = n_a + 8;
#pragma unroll
    for (int nt = 0; nt < 12; nt++) {
        int d = nt * 8 + 2 * q;
        float ra0 = gr[base + (size_t)n_a * HD + d];
        float ra1 = gr[base + (size_t)n_a * HD + d + 1];
        float rb0 = gr[base + (size_t)n_b * HD + d];
        float rb1 = gr[base + (size_t)n_b * HD + d + 1];
        size_t oa = ((size_t)(b_ * SEQ + n_a)) * EMB + h * HD + d;
        size_t ob = ((size_t)(b_ * SEQ + n_b)) * EMB + h * HD + d;
        gatt[oa]     = o[nt][0] * li_a * ra0;
        gatt[oa + 1] = o[nt][1] * li_a * ra1;
        gatt[ob]     = o[nt][2] * li_b * rb0;
        gatt[ob + 1] = o[nt][3] * li_b * rb1;
    }
}

// ===========================================================================
extern "C" void kernel_launch(void* const* d_in, const int* in_sizes, int n_in,
                              void* d_out, int out_size)
{
    const float* x      = (const float*)d_in[0];
    const float* w_qkvr = (const float*)d_in[1];
    const float* b_qkvr = (const float*)d_in[2];
    const float* w_proj = (const float*)d_in[3];
    const float* b_proj = (const float*)d_in[4];
    float* out = (float*)d_out;

    cudaFuncSetAttribute(gemm_qkv,
                         cudaFuncAttributeMaxDynamicSharedMemorySize, QKV_SMEM_BYTES);
    cudaFuncSetAttribute(attn_kernel,
                         cudaFuncAttributeMaxDynamicSharedMemorySize, ATT_SMEM_BYTES);

    float *gq, *gr, *gatt;
    cudaGetSymbolAddress((void**)&gq, g_q);
    cudaGetSymbolAddress((void**)&gr, g_r);
    cudaGetSymbolAddress((void**)&gatt, g_att);

    pack_a<<<MROWS * EMB / 4 / 256, 256>>>(x, MROWS * EMB / 4);
    pack_b<<<KPTOT * (QKVN / 4) / 256, 256>>>(w_qkvr);

    gemm_qkv<<<dim3(QKVN / 128, MROWS / 128), 256, QKV_SMEM_BYTES>>>(b_qkvr);

    pack_k<<<BHTOT * SEQ * 24 / 256, 256>>>();
    pack_v<<<BHTOT * 64 * 32 * 24 / 256, 256>>>();

    attn_kernel<<<dim3(SEQ / 64, BHTOT), 128, ATT_SMEM_BYTES>>>(gq, gr, gatt);
    gemm_proj<<<dim3(EMB / 128, MROWS / 128), 256>>>(gatt, w_proj, b_proj, out, EMB);
}